// round 1
// baseline (speedup 1.0000x reference)
#include <cuda_runtime.h>
#include <math_constants.h>
#include <cstdint>

// Problem constants (B=2, T=2048, C=2048, H=16, D=128)
#define BB   2
#define TT   2048
#define CC   2048
#define HH   16
#define DD   128
#define MTOT (BB*TT)          // 4096
#define N3C  (3*CC)           // 6144

// -------- scratch (static device globals: the allowed scratch path) --------
__device__ float g_q[(size_t)BB*HH*TT*DD];   // [B,H,T,D]
__device__ float g_k[(size_t)BB*HH*TT*DD];
__device__ float g_v[(size_t)BB*HH*TT*DD];
__device__ float g_y[(size_t)BB*TT*CC];      // [B*T, C] attention output

// ============================================================================
// GEMM 1: qkv = x @ w_attn, scattered into g_q/g_k/g_v as [B,H,T,D]
// 128x128 tile, BK=16, 256 threads, 8x8 per thread.
// ============================================================================
__global__ __launch_bounds__(256, 2) void gemm_qkv_kernel(
    const float* __restrict__ A,      // [4096, 2048]
    const float* __restrict__ W)      // [2048, 6144]
{
    __shared__ float As[16][132];     // transposed A tile, padded pitch
    __shared__ float Bs[16][128];

    const int K = CC;
    const int N = N3C;
    const int m0 = blockIdx.y * 128;
    const int n0 = blockIdx.x * 128;
    const int tid = threadIdx.x;
    const int tx = tid & 15, ty = tid >> 4;

    float acc[8][8];
#pragma unroll
    for (int i = 0; i < 8; i++)
#pragma unroll
        for (int j = 0; j < 8; j++) acc[i][j] = 0.f;

    for (int k0 = 0; k0 < K; k0 += 16) {
        // A tile: 128 rows x 16 k  (transpose into As[k][m])
#pragma unroll
        for (int p = 0; p < 2; p++) {
            int v   = tid + p * 256;
            int row = v >> 2;              // 0..127
            int kc  = (v & 3) * 4;         // 0,4,8,12
            float4 f = *(const float4*)(A + (size_t)(m0 + row) * K + k0 + kc);
            As[kc + 0][row] = f.x;
            As[kc + 1][row] = f.y;
            As[kc + 2][row] = f.z;
            As[kc + 3][row] = f.w;
        }
        // B tile: 16 k-rows x 128 n
#pragma unroll
        for (int p = 0; p < 2; p++) {
            int v  = tid + p * 256;
            int kr = v >> 5;               // 0..15
            int nc = (v & 31) * 4;
            *(float4*)&Bs[kr][nc] = *(const float4*)(W + (size_t)(k0 + kr) * N + n0 + nc);
        }
        __syncthreads();

#pragma unroll
        for (int kk = 0; kk < 16; kk++) {
            float a[8], b[8];
            *(float4*)(a)     = *(const float4*)&As[kk][ty * 8];
            *(float4*)(a + 4) = *(const float4*)&As[kk][ty * 8 + 4];
            *(float4*)(b)     = *(const float4*)&Bs[kk][tx * 8];
            *(float4*)(b + 4) = *(const float4*)&Bs[kk][tx * 8 + 4];
#pragma unroll
            for (int i = 0; i < 8; i++)
#pragma unroll
                for (int j = 0; j < 8; j++)
                    acc[i][j] = fmaf(a[i], b[j], acc[i][j]);
        }
        __syncthreads();
    }

    // Epilogue: BN=128 is 128-aligned within one of q/k/v and one head.
    const int which = n0 / CC;            // 0=q 1=k 2=v
    const int c0    = n0 % CC;
    const int h     = c0 >> 7;            // head; d0 == 0 always
    float* dst = (which == 0) ? g_q : (which == 1) ? g_k : g_v;

#pragma unroll
    for (int i = 0; i < 8; i++) {
        int m = m0 + ty * 8 + i;
        int b = m >> 11;                   // m / 2048
        int t = m & 2047;
        float* rowp = dst + ((size_t)((b * HH + h) * TT + t)) * DD + tx * 8;
        float4 o0 = make_float4(acc[i][0], acc[i][1], acc[i][2], acc[i][3]);
        float4 o1 = make_float4(acc[i][4], acc[i][5], acc[i][6], acc[i][7]);
        *(float4*)(rowp)     = o0;
        *(float4*)(rowp + 4) = o1;
    }
}

// ============================================================================
// GEMM 2: out = g_y @ w_proj   (4096x2048 @ 2048x2048)
// ============================================================================
__global__ __launch_bounds__(256, 2) void gemm_proj_kernel(
    const float* __restrict__ W,      // [2048, 2048]
    float* __restrict__ Cout)         // [4096, 2048]
{
    __shared__ float As[16][132];
    __shared__ float Bs[16][128];

    const int K = CC;
    const int N = CC;
    const int m0 = blockIdx.y * 128;
    const int n0 = blockIdx.x * 128;
    const int tid = threadIdx.x;
    const int tx = tid & 15, ty = tid >> 4;
    const float* A = g_y;

    float acc[8][8];
#pragma unroll
    for (int i = 0; i < 8; i++)
#pragma unroll
        for (int j = 0; j < 8; j++) acc[i][j] = 0.f;

    for (int k0 = 0; k0 < K; k0 += 16) {
#pragma unroll
        for (int p = 0; p < 2; p++) {
            int v   = tid + p * 256;
            int row = v >> 2;
            int kc  = (v & 3) * 4;
            float4 f = *(const float4*)(A + (size_t)(m0 + row) * K + k0 + kc);
            As[kc + 0][row] = f.x;
            As[kc + 1][row] = f.y;
            As[kc + 2][row] = f.z;
            As[kc + 3][row] = f.w;
        }
#pragma unroll
        for (int p = 0; p < 2; p++) {
            int v  = tid + p * 256;
            int kr = v >> 5;
            int nc = (v & 31) * 4;
            *(float4*)&Bs[kr][nc] = *(const float4*)(W + (size_t)(k0 + kr) * N + n0 + nc);
        }
        __syncthreads();

#pragma unroll
        for (int kk = 0; kk < 16; kk++) {
            float a[8], b[8];
            *(float4*)(a)     = *(const float4*)&As[kk][ty * 8];
            *(float4*)(a + 4) = *(const float4*)&As[kk][ty * 8 + 4];
            *(float4*)(b)     = *(const float4*)&Bs[kk][tx * 8];
            *(float4*)(b + 4) = *(const float4*)&Bs[kk][tx * 8 + 4];
#pragma unroll
            for (int i = 0; i < 8; i++)
#pragma unroll
                for (int j = 0; j < 8; j++)
                    acc[i][j] = fmaf(a[i], b[j], acc[i][j]);
        }
        __syncthreads();
    }

#pragma unroll
    for (int i = 0; i < 8; i++) {
        int m = m0 + ty * 8 + i;
        float* rowp = Cout + (size_t)m * N + n0 + tx * 8;
        float4 o0 = make_float4(acc[i][0], acc[i][1], acc[i][2], acc[i][3]);
        float4 o1 = make_float4(acc[i][4], acc[i][5], acc[i][6], acc[i][7]);
        *(float4*)(rowp)     = o0;
        *(float4*)(rowp + 4) = o1;
    }
}

// ============================================================================
// Flash attention (fp32, causal). BM=BN=64, D=128, 256 threads.
// smem: Qs[128][65] (d-major), Ks[128][65] (d-major), Vs[64][128], Ps[64][64]
// Thread grid 16x16: S fragment 4x4 (rows=ty*4+i, cols=tx*4+j),
// O fragment 4x8 (rows=ty*4+i, d-cols=tx*8+j).
// ============================================================================
#define QP 65
#define ATT_SMEM ((128*QP + 128*QP + 64*128 + 64*64) * 4)

__global__ __launch_bounds__(256) void flash_attn_kernel()
{
    extern __shared__ float sm[];
    float* Qs = sm;                       // [128][65]
    float* Ks = Qs + 128 * QP;            // [128][65]
    float* Vs = Ks + 128 * QP;            // [64][128]
    float* Ps = Vs + 64 * 128;            // [64][64]

    const int bh  = blockIdx.y;           // b*H + h
    const int qb  = blockIdx.x;           // query tile
    const int tid = threadIdx.x;
    const int tx  = tid & 15, ty = tid >> 4;

    const float* Qg = g_q + (size_t)bh * TT * DD + (size_t)qb * 64 * DD;
    const float* Kg = g_k + (size_t)bh * TT * DD;
    const float* Vg = g_v + (size_t)bh * TT * DD;

    // Load Q tile transposed: Qs[d][m]
#pragma unroll
    for (int p = 0; p < 8; p++) {
        int v   = tid + p * 256;
        int row = v >> 5;                 // token 0..63
        int c4  = (v & 31) * 4;           // d
        float4 f = *(const float4*)(Qg + (size_t)row * DD + c4);
        Qs[(c4 + 0) * QP + row] = f.x;
        Qs[(c4 + 1) * QP + row] = f.y;
        Qs[(c4 + 2) * QP + row] = f.z;
        Qs[(c4 + 3) * QP + row] = f.w;
    }

    float row_max[4], row_sum[4], o[4][8];
#pragma unroll
    for (int i = 0; i < 4; i++) {
        row_max[i] = -CUDART_INF_F;
        row_sum[i] = 0.f;
#pragma unroll
        for (int j = 0; j < 8; j++) o[i][j] = 0.f;
    }
    const float scale = 0.08838834764831845f;   // 1/sqrt(128)

    for (int kb = 0; kb <= qb; kb++) {
        __syncthreads();    // previous iteration done reading Ks/Vs/Ps

        const float* Kt = Kg + (size_t)kb * 64 * DD;
        const float* Vt = Vg + (size_t)kb * 64 * DD;
#pragma unroll
        for (int p = 0; p < 8; p++) {
            int v   = tid + p * 256;
            int row = v >> 5;
            int c4  = (v & 31) * 4;
            float4 f = *(const float4*)(Kt + (size_t)row * DD + c4);
            Ks[(c4 + 0) * QP + row] = f.x;
            Ks[(c4 + 1) * QP + row] = f.y;
            Ks[(c4 + 2) * QP + row] = f.z;
            Ks[(c4 + 3) * QP + row] = f.w;
            float4 g2 = *(const float4*)(Vt + (size_t)row * DD + c4);
            *(float4*)&Vs[row * 128 + c4] = g2;
        }
        __syncthreads();

        // S = Q K^T  (4x4 fragment per thread)
        float s[4][4];
#pragma unroll
        for (int i = 0; i < 4; i++)
#pragma unroll
            for (int j = 0; j < 4; j++) s[i][j] = 0.f;

        for (int d = 0; d < 128; d++) {
            float a[4], b[4];
#pragma unroll
            for (int i = 0; i < 4; i++) a[i] = Qs[d * QP + ty * 4 + i];
#pragma unroll
            for (int j = 0; j < 4; j++) b[j] = Ks[d * QP + tx * 4 + j];
#pragma unroll
            for (int i = 0; i < 4; i++)
#pragma unroll
                for (int j = 0; j < 4; j++)
                    s[i][j] = fmaf(a[i], b[j], s[i][j]);
        }

        // scale + causal mask on diagonal tile
#pragma unroll
        for (int i = 0; i < 4; i++)
#pragma unroll
            for (int j = 0; j < 4; j++) s[i][j] *= scale;
        if (kb == qb) {
#pragma unroll
            for (int i = 0; i < 4; i++)
#pragma unroll
                for (int j = 0; j < 4; j++)
                    if (tx * 4 + j > ty * 4 + i) s[i][j] = -CUDART_INF_F;
        }

        // online softmax; row groups = 16 lanes (same ty), aligned in-warp
#pragma unroll
        for (int i = 0; i < 4; i++) {
            float mx = s[i][0];
#pragma unroll
            for (int j = 1; j < 4; j++) mx = fmaxf(mx, s[i][j]);
#pragma unroll
            for (int off = 8; off > 0; off >>= 1)
                mx = fmaxf(mx, __shfl_xor_sync(0xffffffffu, mx, off, 16));

            float nm   = fmaxf(row_max[i], mx);
            float corr = __expf(row_max[i] - nm);   // 0 on first tile
            row_max[i] = nm;

            float p0[4], psum = 0.f;
#pragma unroll
            for (int j = 0; j < 4; j++) {
                p0[j] = __expf(s[i][j] - nm);       // masked -> 0
                psum += p0[j];
            }
#pragma unroll
            for (int off = 8; off > 0; off >>= 1)
                psum += __shfl_xor_sync(0xffffffffu, psum, off, 16);

            row_sum[i] = row_sum[i] * corr + psum;
#pragma unroll
            for (int j = 0; j < 8; j++) o[i][j] *= corr;
#pragma unroll
            for (int j = 0; j < 4; j++)
                Ps[(ty * 4 + i) * 64 + tx * 4 + j] = p0[j];
        }
        __syncthreads();

        // O += P @ V
        for (int n = 0; n < 64; n++) {
            float vv[8];
            *(float4*)(vv)     = *(const float4*)&Vs[n * 128 + tx * 8];
            *(float4*)(vv + 4) = *(const float4*)&Vs[n * 128 + tx * 8 + 4];
            float pr[4];
#pragma unroll
            for (int i = 0; i < 4; i++) pr[i] = Ps[(ty * 4 + i) * 64 + n];
#pragma unroll
            for (int i = 0; i < 4; i++)
#pragma unroll
                for (int j = 0; j < 8; j++)
                    o[i][j] = fmaf(pr[i], vv[j], o[i][j]);
        }
    }

    // finalize + write to g_y in [B,T,C] layout
    const int b = bh >> 4;
    const int h = bh & 15;
#pragma unroll
    for (int i = 0; i < 4; i++) {
        float inv = 1.f / row_sum[i];
        int t = qb * 64 + ty * 4 + i;
        float* yp = g_y + ((size_t)(b * TT + t)) * CC + h * DD + tx * 8;
        float4 o0 = make_float4(o[i][0] * inv, o[i][1] * inv, o[i][2] * inv, o[i][3] * inv);
        float4 o1 = make_float4(o[i][4] * inv, o[i][5] * inv, o[i][6] * inv, o[i][7] * inv);
        *(float4*)(yp)     = o0;
        *(float4*)(yp + 4) = o1;
    }
}

// ============================================================================
extern "C" void kernel_launch(void* const* d_in, const int* in_sizes, int n_in,
                              void* d_out, int out_size)
{
    const float* x      = (const float*)d_in[0];   // [2,2048,2048]
    const float* w_attn = (const float*)d_in[1];   // [2048,6144]
    const float* w_proj = (const float*)d_in[2];   // [2048,2048]
    float* out = (float*)d_out;                    // [2,2048,2048]

    // 1) QKV projection
    gemm_qkv_kernel<<<dim3(N3C / 128, MTOT / 128), 256>>>(x, w_attn);

    // 2) causal flash attention
    cudaFuncSetAttribute(flash_attn_kernel,
                         cudaFuncAttributeMaxDynamicSharedMemorySize, ATT_SMEM);
    flash_attn_kernel<<<dim3(TT / 64, BB * HH), 256, ATT_SMEM>>>();

    // 3) output projection
    gemm_proj_kernel<<<dim3(CC / 128, MTOT / 128), 256>>>(w_proj, out);
}

// round 3
// speedup vs baseline: 1.6654x; 1.6654x over previous
#include <cuda_runtime.h>
#include <cuda_bf16.h>
#include <math_constants.h>
#include <cstdint>

// Problem constants (B=2, T=2048, C=2048, H=16, D=128)
#define BB   2
#define TT   2048
#define CC   2048
#define HH   16
#define DD   128
#define MTOT (BB*TT)          // 4096
#define N3C  (3*CC)           // 6144
#define KDIM 2048

typedef __nv_bfloat16 bf16;

// -------- scratch (static device globals: the allowed scratch path) --------
__device__ float g_q[(size_t)BB*HH*TT*DD];   // [B,H,T,D]
__device__ float g_k[(size_t)BB*HH*TT*DD];
__device__ float g_v[(size_t)BB*HH*TT*DD];
__device__ bf16  g_xhi[(size_t)MTOT*KDIM];   // x split
__device__ bf16  g_xlo[(size_t)MTOT*KDIM];
__device__ bf16  g_yhi[(size_t)MTOT*KDIM];   // attention out split
__device__ bf16  g_ylo[(size_t)MTOT*KDIM];
__device__ bf16  g_wqhi[(size_t)N3C*KDIM];   // w_attn^T split [N][K]
__device__ bf16  g_wqlo[(size_t)N3C*KDIM];
__device__ bf16  g_wphi[(size_t)CC*KDIM];    // w_proj^T split [N][K]
__device__ bf16  g_wplo[(size_t)CC*KDIM];

// ============================================================================
// helpers
// ============================================================================
__device__ __forceinline__ uint32_t smem_u32(const void* p) {
    uint32_t a;
    asm("{ .reg .u64 t; cvta.to.shared.u64 t, %1; cvt.u32.u64 %0, t; }"
        : "=r"(a) : "l"(p));
    return a;
}
__device__ __forceinline__ void split_bf16(float v, bf16& h, bf16& l) {
    h = __float2bfloat16_rn(v);
    l = __float2bfloat16_rn(v - __bfloat162float(h));
}
#define CP16(dst, src) \
    asm volatile("cp.async.cg.shared.global [%0], [%1], 16;" \
                 :: "r"(dst), "l"(src))
#define CP_COMMIT() asm volatile("cp.async.commit_group;")
#define CP_WAIT(n)  asm volatile("cp.async.wait_group %0;" :: "n"(n))

__device__ __forceinline__ void ldsm_x4(uint32_t* r, uint32_t addr) {
    asm volatile("ldmatrix.sync.aligned.m8n8.x4.shared.b16 {%0,%1,%2,%3}, [%4];"
        : "=r"(r[0]), "=r"(r[1]), "=r"(r[2]), "=r"(r[3]) : "r"(addr));
}
__device__ __forceinline__ void ldsm_x2(uint32_t* r, uint32_t addr) {
    asm volatile("ldmatrix.sync.aligned.m8n8.x2.shared.b16 {%0,%1}, [%2];"
        : "=r"(r[0]), "=r"(r[1]) : "r"(addr));
}
__device__ __forceinline__ void mma16816(float* c, const uint32_t* a,
                                         const uint32_t* b) {
    asm volatile(
        "mma.sync.aligned.m16n8k16.row.col.f32.bf16.bf16.f32 "
        "{%0,%1,%2,%3}, {%4,%5,%6,%7}, {%8,%9}, {%0,%1,%2,%3};"
        : "+f"(c[0]), "+f"(c[1]), "+f"(c[2]), "+f"(c[3])
        : "r"(a[0]), "r"(a[1]), "r"(a[2]), "r"(a[3]), "r"(b[0]), "r"(b[1]));
}

// ============================================================================
// Prep kernels
// ============================================================================
// x [M][K] fp32 -> hi/lo bf16 same layout. 4 floats per thread.
__global__ __launch_bounds__(256) void split_x_kernel(
    const float* __restrict__ X, bf16* __restrict__ Hi, bf16* __restrict__ Lo)
{
    size_t i4 = (size_t)blockIdx.x * 256 + threadIdx.x;
    float4 v = ((const float4*)X)[i4];
    bf16 h[4], l[4];
    split_bf16(v.x, h[0], l[0]); split_bf16(v.y, h[1], l[1]);
    split_bf16(v.z, h[2], l[2]); split_bf16(v.w, h[3], l[3]);
    *(uint2*)(Hi + i4 * 4) = *(uint2*)h;
    *(uint2*)(Lo + i4 * 4) = *(uint2*)l;
}

// W [K][N] fp32 -> W^T [N][K] bf16 hi/lo. Tile 64k x 32n.
__global__ __launch_bounds__(256) void prep_w_kernel(
    const float* __restrict__ W, bf16* __restrict__ Hi, bf16* __restrict__ Lo,
    int N)
{
    __shared__ float s[32][65];           // [n][k] transposed
    const int k0 = blockIdx.y * 64;
    const int n0 = blockIdx.x * 32;
    const int tid = threadIdx.x;
    const int nn = tid & 31, kk = tid >> 5;      // kk 0..7
#pragma unroll
    for (int i = 0; i < 8; i++) {
        int k = kk + i * 8;
        s[nn][k] = __ldg(W + (size_t)(k0 + k) * N + n0 + nn);
    }
    __syncthreads();
    const int n = tid >> 3, kc = (tid & 7) * 8;
    bf16 h[8], l[8];
#pragma unroll
    for (int j = 0; j < 8; j++) split_bf16(s[n][kc + j], h[j], l[j]);
    size_t o = (size_t)(n0 + n) * KDIM + k0 + kc;
    *(uint4*)(Hi + o) = *(uint4*)h;
    *(uint4*)(Lo + o) = *(uint4*)l;
}

// ============================================================================
// bf16x3 GEMM via mma.sync: C[M,N] = A[M,K] @ B^T[N,K]
// 128x128x32 CTA tile, 8 warps (2x4), warp tile 64x32, double-buffered cp.async.
// MODE 0: scatter into g_q/g_k/g_v; MODE 1: row-major Cout [M][CC].
// ============================================================================
#define AH 0
#define AL 10240
#define BH 20480
#define BL 30720
#define STG 40960
#define GEMM_SMEM (2*STG)
#define NCHUNK (KDIM/32)      // 64

template<int MODE>
__global__ __launch_bounds__(256, 2) void gemm_bf16x3_kernel(
    const bf16* __restrict__ Ahi, const bf16* __restrict__ Alo,
    const bf16* __restrict__ Bhi, const bf16* __restrict__ Blo,
    float* __restrict__ Cout)
{
    extern __shared__ char smem[];
    const uint32_t sb = smem_u32(smem);
    const int tid  = threadIdx.x;
    const int lane = tid & 31, wid = tid >> 5;
    const int wm = wid & 1, wn = wid >> 1;       // warp grid 2 x 4
    const int m0 = blockIdx.y * 128;
    const int n0 = blockIdx.x * 128;

    float acc[4][4][4];
#pragma unroll
    for (int mi = 0; mi < 4; mi++)
#pragma unroll
        for (int ni = 0; ni < 4; ni++)
#pragma unroll
            for (int f = 0; f < 4; f++) acc[mi][ni][f] = 0.f;

    // per-thread ldmatrix base offsets (stage 0, ks 0, mi/ni 0)
    const uint32_t aBase = sb + AH + (wm * 64 + (lane & 15)) * 80
                         + (lane >> 4) * 16;
    const uint32_t bBase = sb + BH + (wn * 32 + (lane & 7)) * 80
                         + ((lane >> 3) & 1) * 16;

    // loader lambda: chunk c into stage st
    const int lrow = tid >> 1;                 // wrong granularity; use o-loop
    (void)lrow;

#define LOAD_CHUNK(c, st) do {                                                 \
    uint32_t s0 = sb + (st) * STG;                                             \
    _Pragma("unroll")                                                          \
    for (int p = 0; p < 2; p++) {                                              \
        int o   = tid + p * 256;          /* 0..511 */                         \
        int row = o >> 2, ch = o & 3;                                          \
        uint32_t dofs = row * 80 + ch * 16;                                    \
        size_t ga = (size_t)(m0 + row) * KDIM + (c) * 32 + ch * 8;             \
        size_t gb = (size_t)(n0 + row) * KDIM + (c) * 32 + ch * 8;             \
        CP16(s0 + AH + dofs, Ahi + ga);                                        \
        CP16(s0 + AL + dofs, Alo + ga);                                        \
        CP16(s0 + BH + dofs, Bhi + gb);                                        \
        CP16(s0 + BL + dofs, Blo + gb);                                        \
    }                                                                          \
} while (0)

    LOAD_CHUNK(0, 0);
    CP_COMMIT();

    for (int c = 0; c < NCHUNK; c++) {
        const int st = c & 1;
        if (c + 1 < NCHUNK) {
            LOAD_CHUNK(c + 1, st ^ 1);
            CP_COMMIT();
            CP_WAIT(1);
        } else {
            CP_WAIT(0);
        }
        __syncthreads();

        const uint32_t sStage = st * STG;
#pragma unroll
        for (int ks = 0; ks < 2; ks++) {
            const uint32_t kOfs = sStage + ks * 32;
            uint32_t aw[4][4], bw[4][2], bw2[4][2];
#pragma unroll
            for (int mi = 0; mi < 4; mi++)
                ldsm_x4(aw[mi], aBase + kOfs + mi * (16 * 80));
#pragma unroll
            for (int ni = 0; ni < 4; ni++) {
                ldsm_x2(bw[ni],  bBase + kOfs + ni * (8 * 80));
                ldsm_x2(bw2[ni], bBase + kOfs + ni * (8 * 80) + (BL - BH));
            }
            // hi*hi
#pragma unroll
            for (int mi = 0; mi < 4; mi++)
#pragma unroll
                for (int ni = 0; ni < 4; ni++)
                    mma16816(acc[mi][ni], aw[mi], bw[ni]);
            // hi*lo
#pragma unroll
            for (int mi = 0; mi < 4; mi++)
#pragma unroll
                for (int ni = 0; ni < 4; ni++)
                    mma16816(acc[mi][ni], aw[mi], bw2[ni]);
            // lo*hi (reuse aw registers)
#pragma unroll
            for (int mi = 0; mi < 4; mi++)
                ldsm_x4(aw[mi], aBase + kOfs + mi * (16 * 80) + (AL - AH));
#pragma unroll
            for (int mi = 0; mi < 4; mi++)
#pragma unroll
                for (int ni = 0; ni < 4; ni++)
                    mma16816(acc[mi][ni], aw[mi], bw[ni]);
        }
        __syncthreads();
    }

    // ---- epilogue ----
    const int lr = lane >> 2, lc = (lane & 3) * 2;
#pragma unroll
    for (int mi = 0; mi < 4; mi++) {
#pragma unroll
        for (int ni = 0; ni < 4; ni++) {
            int mrow = m0 + wm * 64 + mi * 16 + lr;
            int col  = wn * 32 + ni * 8 + lc;         // 0..127 within tile
            float* p0;
            float* p1;
            if (MODE == 0) {
                const int nb = blockIdx.x;
                const int which = nb >> 4, head = nb & 15;
                float* base = (which == 0) ? g_q : (which == 1) ? g_k : g_v;
                int b = mrow >> 11, t = mrow & 2047;
                float* r = base + ((size_t)((b * HH + head) * TT + t)) * DD + col;
                p0 = r;
                int mrow1 = mrow + 8;
                int b1 = mrow1 >> 11, t1 = mrow1 & 2047;
                p1 = base + ((size_t)((b1 * HH + head) * TT + t1)) * DD + col;
            } else {
                p0 = Cout + (size_t)mrow * CC + n0 + col;
                p1 = p0 + (size_t)8 * CC;
            }
            *(float2*)p0 = make_float2(acc[mi][ni][0], acc[mi][ni][1]);
            *(float2*)p1 = make_float2(acc[mi][ni][2], acc[mi][ni][3]);
        }
    }
#undef LOAD_CHUNK
}

// ============================================================================
// Flash attention (fp32, causal). BM=BN=64, D=128, 256 threads.
// Epilogue writes bf16 hi/lo pairs for the proj GEMM.
// ============================================================================
#define QP 65
#define ATT_SMEM ((128*QP + 128*QP + 64*128 + 64*64) * 4)

__global__ __launch_bounds__(256) void flash_attn_kernel()
{
    extern __shared__ float sm[];
    float* Qs = sm;                       // [128][65]
    float* Ks = Qs + 128 * QP;            // [128][65]
    float* Vs = Ks + 128 * QP;            // [64][128]
    float* Ps = Vs + 64 * 128;            // [64][64]

    const int bh  = blockIdx.y;
    const int qb  = blockIdx.x;
    const int tid = threadIdx.x;
    const int tx  = tid & 15, ty = tid >> 4;

    const float* Qg = g_q + (size_t)bh * TT * DD + (size_t)qb * 64 * DD;
    const float* Kg = g_k + (size_t)bh * TT * DD;
    const float* Vg = g_v + (size_t)bh * TT * DD;

#pragma unroll
    for (int p = 0; p < 8; p++) {
        int v   = tid + p * 256;
        int row = v >> 5;
        int c4  = (v & 31) * 4;
        float4 f = *(const float4*)(Qg + (size_t)row * DD + c4);
        Qs[(c4 + 0) * QP + row] = f.x;
        Qs[(c4 + 1) * QP + row] = f.y;
        Qs[(c4 + 2) * QP + row] = f.z;
        Qs[(c4 + 3) * QP + row] = f.w;
    }

    float row_max[4], row_sum[4], o[4][8];
#pragma unroll
    for (int i = 0; i < 4; i++) {
        row_max[i] = -CUDART_INF_F;
        row_sum[i] = 0.f;
#pragma unroll
        for (int j = 0; j < 8; j++) o[i][j] = 0.f;
    }
    const float scale = 0.08838834764831845f;

    for (int kb = 0; kb <= qb; kb++) {
        __syncthreads();
        const float* Kt = Kg + (size_t)kb * 64 * DD;
        const float* Vt = Vg + (size_t)kb * 64 * DD;
#pragma unroll
        for (int p = 0; p < 8; p++) {
            int v   = tid + p * 256;
            int row = v >> 5;
            int c4  = (v & 31) * 4;
            float4 f = *(const float4*)(Kt + (size_t)row * DD + c4);
            Ks[(c4 + 0) * QP + row] = f.x;
            Ks[(c4 + 1) * QP + row] = f.y;
            Ks[(c4 + 2) * QP + row] = f.z;
            Ks[(c4 + 3) * QP + row] = f.w;
            float4 g2 = *(const float4*)(Vt + (size_t)row * DD + c4);
            *(float4*)&Vs[row * 128 + c4] = g2;
        }
        __syncthreads();

        float s[4][4];
#pragma unroll
        for (int i = 0; i < 4; i++)
#pragma unroll
            for (int j = 0; j < 4; j++) s[i][j] = 0.f;

        for (int d = 0; d < 128; d++) {
            float a[4], b[4];
#pragma unroll
            for (int i = 0; i < 4; i++) a[i] = Qs[d * QP + ty * 4 + i];
#pragma unroll
            for (int j = 0; j < 4; j++) b[j] = Ks[d * QP + tx * 4 + j];
#pragma unroll
            for (int i = 0; i < 4; i++)
#pragma unroll
                for (int j = 0; j < 4; j++)
                    s[i][j] = fmaf(a[i], b[j], s[i][j]);
        }

#pragma unroll
        for (int i = 0; i < 4; i++)
#pragma unroll
            for (int j = 0; j < 4; j++) s[i][j] *= scale;
        if (kb == qb) {
#pragma unroll
            for (int i = 0; i < 4; i++)
#pragma unroll
                for (int j = 0; j < 4; j++)
                    if (tx * 4 + j > ty * 4 + i) s[i][j] = -CUDART_INF_F;
        }

#pragma unroll
        for (int i = 0; i < 4; i++) {
            float mx = s[i][0];
#pragma unroll
            for (int j = 1; j < 4; j++) mx = fmaxf(mx, s[i][j]);
#pragma unroll
            for (int off = 8; off > 0; off >>= 1)
                mx = fmaxf(mx, __shfl_xor_sync(0xffffffffu, mx, off, 16));

            float nm   = fmaxf(row_max[i], mx);
            float corr = __expf(row_max[i] - nm);
            row_max[i] = nm;

            float p0[4], psum = 0.f;
#pragma unroll
            for (int j = 0; j < 4; j++) {
                p0[j] = __expf(s[i][j] - nm);
                psum += p0[j];
            }
#pragma unroll
            for (int off = 8; off > 0; off >>= 1)
                psum += __shfl_xor_sync(0xffffffffu, psum, off, 16);

            row_sum[i] = row_sum[i] * corr + psum;
#pragma unroll
            for (int j = 0; j < 8; j++) o[i][j] *= corr;
#pragma unroll
            for (int j = 0; j < 4; j++)
                Ps[(ty * 4 + i) * 64 + tx * 4 + j] = p0[j];
        }
        __syncthreads();

        for (int n = 0; n < 64; n++) {
            float vv[8];
            *(float4*)(vv)     = *(const float4*)&Vs[n * 128 + tx * 8];
            *(float4*)(vv + 4) = *(const float4*)&Vs[n * 128 + tx * 8 + 4];
            float pr[4];
#pragma unroll
            for (int i = 0; i < 4; i++) pr[i] = Ps[(ty * 4 + i) * 64 + n];
#pragma unroll
            for (int i = 0; i < 4; i++)
#pragma unroll
                for (int j = 0; j < 8; j++)
                    o[i][j] = fmaf(pr[i], vv[j], o[i][j]);
        }
    }

    const int b = bh >> 4;
    const int h = bh & 15;
#pragma unroll
    for (int i = 0; i < 4; i++) {
        float inv = 1.f / row_sum[i];
        int t = qb * 64 + ty * 4 + i;
        size_t base = ((size_t)(b * TT + t)) * CC + h * DD + tx * 8;
        bf16 hh[8], ll[8];
#pragma unroll
        for (int j = 0; j < 8; j++) split_bf16(o[i][j] * inv, hh[j], ll[j]);
        *(uint4*)(g_yhi + base) = *(uint4*)hh;
        *(uint4*)(g_ylo + base) = *(uint4*)ll;
    }
}

// ============================================================================
extern "C" void kernel_launch(void* const* d_in, const int* in_sizes, int n_in,
                              void* d_out, int out_size)
{
    const float* x      = (const float*)d_in[0];   // [2,2048,2048]
    const float* w_attn = (const float*)d_in[1];   // [2048,6144]
    const float* w_proj = (const float*)d_in[2];   // [2048,2048]
    float* out = (float*)d_out;                    // [2,2048,2048]

    bf16 *xhi, *xlo, *yhi, *ylo, *wqhi, *wqlo, *wphi, *wplo;
    cudaGetSymbolAddress((void**)&xhi,  g_xhi);
    cudaGetSymbolAddress((void**)&xlo,  g_xlo);
    cudaGetSymbolAddress((void**)&yhi,  g_yhi);
    cudaGetSymbolAddress((void**)&ylo,  g_ylo);
    cudaGetSymbolAddress((void**)&wqhi, g_wqhi);
    cudaGetSymbolAddress((void**)&wqlo, g_wqlo);
    cudaGetSymbolAddress((void**)&wphi, g_wphi);
    cudaGetSymbolAddress((void**)&wplo, g_wplo);

    cudaFuncSetAttribute(gemm_bf16x3_kernel<0>,
                         cudaFuncAttributeMaxDynamicSharedMemorySize, GEMM_SMEM);
    cudaFuncSetAttribute(gemm_bf16x3_kernel<1>,
                         cudaFuncAttributeMaxDynamicSharedMemorySize, GEMM_SMEM);
    cudaFuncSetAttribute(flash_attn_kernel,
                         cudaFuncAttributeMaxDynamicSharedMemorySize, ATT_SMEM);

    // 0) prep: split x, transpose+split weights
    split_x_kernel<<<(size_t)MTOT * KDIM / 4 / 256, 256>>>(x, xhi, xlo);
    prep_w_kernel<<<dim3(N3C / 32, KDIM / 64), 256>>>(w_attn, wqhi, wqlo, N3C);
    prep_w_kernel<<<dim3(CC  / 32, KDIM / 64), 256>>>(w_proj, wphi, wplo, CC);

    // 1) QKV projection (bf16x3 mma.sync), scatter to g_q/g_k/g_v
    gemm_bf16x3_kernel<0><<<dim3(N3C / 128, MTOT / 128), 256, GEMM_SMEM>>>(
        xhi, xlo, wqhi, wqlo, nullptr);

    // 2) causal flash attention -> g_yhi/g_ylo
    flash_attn_kernel<<<dim3(TT / 64, BB * HH), 256, ATT_SMEM>>>();

    // 3) output projection (bf16x3 mma.sync) -> out
    gemm_bf16x3_kernel<1><<<dim3(CC / 128, MTOT / 128), 256, GEMM_SMEM>>>(
        yhi, ylo, wphi, wplo, out);
}

// round 4
// speedup vs baseline: 2.9185x; 1.7524x over previous
#include <cuda_runtime.h>
#include <cuda_bf16.h>
#include <math_constants.h>
#include <cstdint>

// Problem constants (B=2, T=2048, C=2048, H=16, D=128)
#define BB   2
#define TT   2048
#define CC   2048
#define HH   16
#define DD   128
#define MTOT (BB*TT)          // 4096
#define N3C  (3*CC)           // 6144
#define KDIM 2048

typedef __nv_bfloat16 bf16;

// -------- scratch (static device globals: the allowed scratch path) --------
__device__ bf16 g_qhi[(size_t)BB*HH*TT*DD];  // q pre-scaled, split
__device__ bf16 g_qlo[(size_t)BB*HH*TT*DD];
__device__ bf16 g_khi[(size_t)BB*HH*TT*DD];
__device__ bf16 g_klo[(size_t)BB*HH*TT*DD];
__device__ bf16 g_vhi[(size_t)BB*HH*TT*DD];
__device__ bf16 g_vlo[(size_t)BB*HH*TT*DD];
__device__ bf16 g_xhi[(size_t)MTOT*KDIM];    // x split
__device__ bf16 g_xlo[(size_t)MTOT*KDIM];
__device__ bf16 g_yhi[(size_t)MTOT*KDIM];    // attention out split
__device__ bf16 g_ylo[(size_t)MTOT*KDIM];
__device__ bf16 g_wqhi[(size_t)N3C*KDIM];    // w_attn^T split [N][K]
__device__ bf16 g_wqlo[(size_t)N3C*KDIM];
__device__ bf16 g_wphi[(size_t)CC*KDIM];     // w_proj^T split [N][K]
__device__ bf16 g_wplo[(size_t)CC*KDIM];

// ============================================================================
// helpers
// ============================================================================
__device__ __forceinline__ uint32_t smem_u32(const void* p) {
    uint32_t a;
    asm("{ .reg .u64 t; cvta.to.shared.u64 t, %1; cvt.u32.u64 %0, t; }"
        : "=r"(a) : "l"(p));
    return a;
}
__device__ __forceinline__ void split_bf16(float v, bf16& h, bf16& l) {
    h = __float2bfloat16_rn(v);
    l = __float2bfloat16_rn(v - __bfloat162float(h));
}
// returns (bf16(a) in low 16) | (bf16(b) in high 16)
__device__ __forceinline__ uint32_t pack2_hi(float a, float b) {
    uint32_t r;
    asm("cvt.rn.bf16x2.f32 %0, %1, %2;" : "=r"(r) : "f"(b), "f"(a));
    return r;
}
__device__ __forceinline__ uint32_t pack2_lo(float a, float b) {
    float ah = __bfloat162float(__float2bfloat16_rn(a));
    float bh = __bfloat162float(__float2bfloat16_rn(b));
    return pack2_hi(a - ah, b - bh);
}
#define CP16(dst, src) \
    asm volatile("cp.async.cg.shared.global [%0], [%1], 16;" \
                 :: "r"(dst), "l"(src))
#define CP_COMMIT() asm volatile("cp.async.commit_group;")
#define CP_WAIT(n)  asm volatile("cp.async.wait_group %0;" :: "n"(n))

__device__ __forceinline__ void ldsm_x4(uint32_t* r, uint32_t addr) {
    asm volatile("ldmatrix.sync.aligned.m8n8.x4.shared.b16 {%0,%1,%2,%3}, [%4];"
        : "=r"(r[0]), "=r"(r[1]), "=r"(r[2]), "=r"(r[3]) : "r"(addr));
}
__device__ __forceinline__ void ldsm_x4_t(uint32_t* r, uint32_t addr) {
    asm volatile("ldmatrix.sync.aligned.m8n8.x4.trans.shared.b16 {%0,%1,%2,%3}, [%4];"
        : "=r"(r[0]), "=r"(r[1]), "=r"(r[2]), "=r"(r[3]) : "r"(addr));
}
__device__ __forceinline__ void ldsm_x2(uint32_t* r, uint32_t addr) {
    asm volatile("ldmatrix.sync.aligned.m8n8.x2.shared.b16 {%0,%1}, [%2];"
        : "=r"(r[0]), "=r"(r[1]) : "r"(addr));
}
__device__ __forceinline__ void mma16816(float* c, const uint32_t* a,
                                         const uint32_t* b) {
    asm volatile(
        "mma.sync.aligned.m16n8k16.row.col.f32.bf16.bf16.f32 "
        "{%0,%1,%2,%3}, {%4,%5,%6,%7}, {%8,%9}, {%0,%1,%2,%3};"
        : "+f"(c[0]), "+f"(c[1]), "+f"(c[2]), "+f"(c[3])
        : "r"(a[0]), "r"(a[1]), "r"(a[2]), "r"(a[3]), "r"(b[0]), "r"(b[1]));
}

// ============================================================================
// Prep kernels
// ============================================================================
__global__ __launch_bounds__(256) void split_x_kernel(
    const float* __restrict__ X, bf16* __restrict__ Hi, bf16* __restrict__ Lo)
{
    size_t i4 = (size_t)blockIdx.x * 256 + threadIdx.x;
    float4 v = ((const float4*)X)[i4];
    bf16 h[4], l[4];
    split_bf16(v.x, h[0], l[0]); split_bf16(v.y, h[1], l[1]);
    split_bf16(v.z, h[2], l[2]); split_bf16(v.w, h[3], l[3]);
    *(uint2*)(Hi + i4 * 4) = *(uint2*)h;
    *(uint2*)(Lo + i4 * 4) = *(uint2*)l;
}

__global__ __launch_bounds__(256) void prep_w_kernel(
    const float* __restrict__ W, bf16* __restrict__ Hi, bf16* __restrict__ Lo,
    int N)
{
    __shared__ float s[32][65];           // [n][k] transposed
    const int k0 = blockIdx.y * 64;
    const int n0 = blockIdx.x * 32;
    const int tid = threadIdx.x;
    const int nn = tid & 31, kk = tid >> 5;
#pragma unroll
    for (int i = 0; i < 8; i++) {
        int k = kk + i * 8;
        s[nn][k] = __ldg(W + (size_t)(k0 + k) * N + n0 + nn);
    }
    __syncthreads();
    const int n = tid >> 3, kc = (tid & 7) * 8;
    bf16 h[8], l[8];
#pragma unroll
    for (int j = 0; j < 8; j++) split_bf16(s[n][kc + j], h[j], l[j]);
    size_t o = (size_t)(n0 + n) * KDIM + k0 + kc;
    *(uint4*)(Hi + o) = *(uint4*)h;
    *(uint4*)(Lo + o) = *(uint4*)l;
}

// ============================================================================
// bf16x3 GEMM via mma.sync: C[M,N] = A[M,K] @ B^T[N,K]
// MODE 0: split+scatter into g_{q,k,v}{hi,lo}; MODE 1: fp32 row-major Cout.
// ============================================================================
#define AH 0
#define AL 10240
#define BH 20480
#define BL 30720
#define STG 40960
#define GEMM_SMEM (2*STG)
#define NCHUNK (KDIM/32)      // 64

template<int MODE>
__global__ __launch_bounds__(256, 2) void gemm_bf16x3_kernel(
    const bf16* __restrict__ Ahi, const bf16* __restrict__ Alo,
    const bf16* __restrict__ Bhi, const bf16* __restrict__ Blo,
    float* __restrict__ Cout)
{
    extern __shared__ char smem[];
    const uint32_t sb = smem_u32(smem);
    const int tid  = threadIdx.x;
    const int lane = tid & 31, wid = tid >> 5;
    const int wm = wid & 1, wn = wid >> 1;       // warp grid 2 x 4
    const int m0 = blockIdx.y * 128;
    const int n0 = blockIdx.x * 128;

    float acc[4][4][4];
#pragma unroll
    for (int mi = 0; mi < 4; mi++)
#pragma unroll
        for (int ni = 0; ni < 4; ni++)
#pragma unroll
            for (int f = 0; f < 4; f++) acc[mi][ni][f] = 0.f;

    const uint32_t aBase = sb + AH + (wm * 64 + (lane & 15)) * 80
                         + (lane >> 4) * 16;
    const uint32_t bBase = sb + BH + (wn * 32 + (lane & 7)) * 80
                         + ((lane >> 3) & 1) * 16;

#define LOAD_CHUNK(c, st) do {                                                 \
    uint32_t s0 = sb + (st) * STG;                                             \
    _Pragma("unroll")                                                          \
    for (int p = 0; p < 2; p++) {                                              \
        int o   = tid + p * 256;                                               \
        int row = o >> 2, ch = o & 3;                                          \
        uint32_t dofs = row * 80 + ch * 16;                                    \
        size_t ga = (size_t)(m0 + row) * KDIM + (c) * 32 + ch * 8;             \
        size_t gb = (size_t)(n0 + row) * KDIM + (c) * 32 + ch * 8;             \
        CP16(s0 + AH + dofs, Ahi + ga);                                        \
        CP16(s0 + AL + dofs, Alo + ga);                                        \
        CP16(s0 + BH + dofs, Bhi + gb);                                        \
        CP16(s0 + BL + dofs, Blo + gb);                                        \
    }                                                                          \
} while (0)

    LOAD_CHUNK(0, 0);
    CP_COMMIT();

    for (int c = 0; c < NCHUNK; c++) {
        const int st = c & 1;
        if (c + 1 < NCHUNK) {
            LOAD_CHUNK(c + 1, st ^ 1);
            CP_COMMIT();
            CP_WAIT(1);
        } else {
            CP_WAIT(0);
        }
        __syncthreads();

        const uint32_t sStage = st * STG;
#pragma unroll
        for (int ks = 0; ks < 2; ks++) {
            const uint32_t kOfs = sStage + ks * 32;
            uint32_t aw[4][4], bw[4][2], bw2[4][2];
#pragma unroll
            for (int mi = 0; mi < 4; mi++)
                ldsm_x4(aw[mi], aBase + kOfs + mi * (16 * 80));
#pragma unroll
            for (int ni = 0; ni < 4; ni++) {
                ldsm_x2(bw[ni],  bBase + kOfs + ni * (8 * 80));
                ldsm_x2(bw2[ni], bBase + kOfs + ni * (8 * 80) + (BL - BH));
            }
#pragma unroll
            for (int mi = 0; mi < 4; mi++)
#pragma unroll
                for (int ni = 0; ni < 4; ni++)
                    mma16816(acc[mi][ni], aw[mi], bw[ni]);
#pragma unroll
            for (int mi = 0; mi < 4; mi++)
#pragma unroll
                for (int ni = 0; ni < 4; ni++)
                    mma16816(acc[mi][ni], aw[mi], bw2[ni]);
#pragma unroll
            for (int mi = 0; mi < 4; mi++)
                ldsm_x4(aw[mi], aBase + kOfs + mi * (16 * 80) + (AL - AH));
#pragma unroll
            for (int mi = 0; mi < 4; mi++)
#pragma unroll
                for (int ni = 0; ni < 4; ni++)
                    mma16816(acc[mi][ni], aw[mi], bw[ni]);
        }
        __syncthreads();
    }

    // ---- epilogue ----
    const int lr = lane >> 2, lc = (lane & 3) * 2;
#pragma unroll
    for (int mi = 0; mi < 4; mi++) {
#pragma unroll
        for (int ni = 0; ni < 4; ni++) {
            int mrow = m0 + wm * 64 + mi * 16 + lr;
            int col  = wn * 32 + ni * 8 + lc;
            if (MODE == 0) {
                const int nb = blockIdx.x;
                const int which = nb >> 4, head = nb & 15;
                const float sc = (which == 0) ? 0.08838834764831845f : 1.0f;
                bf16 *hiB, *loB;
                if (which == 0)      { hiB = g_qhi; loB = g_qlo; }
                else if (which == 1) { hiB = g_khi; loB = g_klo; }
                else                 { hiB = g_vhi; loB = g_vlo; }
                int b0 = mrow >> 11, t0 = mrow & 2047;
                int m1 = mrow + 8;
                int b1 = m1 >> 11, t1 = m1 & 2047;
                size_t i0 = ((size_t)((b0 * HH + head) * TT + t0)) * DD + col;
                size_t i1 = ((size_t)((b1 * HH + head) * TT + t1)) * DD + col;
                float v0 = acc[mi][ni][0] * sc, v1 = acc[mi][ni][1] * sc;
                float v2 = acc[mi][ni][2] * sc, v3 = acc[mi][ni][3] * sc;
                *(uint32_t*)(hiB + i0) = pack2_hi(v0, v1);
                *(uint32_t*)(loB + i0) = pack2_lo(v0, v1);
                *(uint32_t*)(hiB + i1) = pack2_hi(v2, v3);
                *(uint32_t*)(loB + i1) = pack2_lo(v2, v3);
            } else {
                float* p0 = Cout + (size_t)mrow * CC + n0 + col;
                float* p1 = p0 + (size_t)8 * CC;
                *(float2*)p0 = make_float2(acc[mi][ni][0], acc[mi][ni][1]);
                *(float2*)p1 = make_float2(acc[mi][ni][2], acc[mi][ni][3]);
            }
        }
    }
#undef LOAD_CHUNK
}

// ============================================================================
// Flash attention on mma.sync (bf16x3). BM=BN=64, D=128, 4 warps, 2 CTAs/SM.
// Warp w owns query rows w*16..w*16+15 (whole rows -> 4-lane shfl softmax).
// ============================================================================
#define FA_PITCH 272        // bytes per 128-bf16 row (256 + 16 pad)
#define FA_KHI 0
#define FA_KLO 17408
#define FA_VHI 34816
#define FA_VLO 52224
#define FA_SMEM 69632

__global__ __launch_bounds__(128, 2) void flash_attn_mma_kernel()
{
    extern __shared__ char smc[];
    const uint32_t sb = smem_u32(smc);
    const int tid  = threadIdx.x;
    const int lane = tid & 31, wid = tid >> 5;
    const int qb = (int)(gridDim.x - 1 - blockIdx.x);   // longest CTAs first
    const int bh = blockIdx.y;

    const size_t bhofs = (size_t)bh * TT * DD;
    const bf16* Qh = g_qhi + bhofs + (size_t)qb * 64 * DD;
    const bf16* Ql = g_qlo + bhofs + (size_t)qb * 64 * DD;

    // ---- stage Q (hi->KHI, lo->KLO), then ldmatrix into registers
#pragma unroll
    for (int p = 0; p < 8; p++) {
        int o = tid + p * 128;
        int row = o >> 4, ch = o & 15;
        uint32_t d = row * FA_PITCH + ch * 16;
        size_t g = (size_t)row * DD + ch * 8;
        CP16(sb + FA_KHI + d, Qh + g);
        CP16(sb + FA_KLO + d, Ql + g);
    }
    CP_COMMIT(); CP_WAIT(0);
    __syncthreads();

    uint32_t qh[8][4], ql[8][4];
    {
        uint32_t qa = sb + FA_KHI + (wid * 16 + (lane & 15)) * FA_PITCH
                    + (lane >> 4) * 16;
#pragma unroll
        for (int ks = 0; ks < 8; ks++) {
            ldsm_x4(qh[ks], qa + ks * 32);
            ldsm_x4(ql[ks], qa + (FA_KLO - FA_KHI) + ks * 32);
        }
    }

    float yacc[16][4];
#pragma unroll
    for (int n = 0; n < 16; n++)
#pragma unroll
        for (int f = 0; f < 4; f++) yacc[n][f] = 0.f;
    float m0r = -CUDART_INF_F, m1r = -CUDART_INF_F;
    float l0r = 0.f, l1r = 0.f;

    const int r0 = lane >> 2;
    const int c0 = (lane & 3) * 2;

    // K (non-trans, two n8 tiles per x4): rows = key
    const uint32_t kaddr = sb + FA_KHI
        + ((lane & 7) + ((lane >> 4) & 1) * 8) * FA_PITCH
        + ((lane >> 3) & 1) * 16;
    // V (trans, two d-tiles per x4): rows = key, col pairs of 8 d
    const uint32_t vaddr = sb + FA_VHI
        + ((lane & 7) + ((lane >> 3) & 1) * 8) * FA_PITCH
        + ((lane >> 4) & 1) * 16;

    for (int kb = 0; kb <= qb; kb++) {
        __syncthreads();      // previous tile fully consumed
        const bf16* Kh = g_khi + bhofs + (size_t)kb * 64 * DD;
        const bf16* Kl = g_klo + bhofs + (size_t)kb * 64 * DD;
        const bf16* Vh = g_vhi + bhofs + (size_t)kb * 64 * DD;
        const bf16* Vl = g_vlo + bhofs + (size_t)kb * 64 * DD;
#pragma unroll
        for (int p = 0; p < 8; p++) {
            int o = tid + p * 128;
            int row = o >> 4, ch = o & 15;
            uint32_t d = row * FA_PITCH + ch * 16;
            size_t g = (size_t)row * DD + ch * 8;
            CP16(sb + FA_KHI + d, Kh + g);
            CP16(sb + FA_KLO + d, Kl + g);
            CP16(sb + FA_VHI + d, Vh + g);
            CP16(sb + FA_VLO + d, Vl + g);
        }
        CP_COMMIT(); CP_WAIT(0);
        __syncthreads();

        // ---- S = Q K^T (3 passes)
        float s[8][4];
#pragma unroll
        for (int j = 0; j < 8; j++)
#pragma unroll
            for (int f = 0; f < 4; f++) s[j][f] = 0.f;

#pragma unroll
        for (int ks = 0; ks < 8; ks++) {
            uint32_t kf[4][4];
#pragma unroll
            for (int jj = 0; jj < 4; jj++)
                ldsm_x4(kf[jj], kaddr + jj * (16 * FA_PITCH) + ks * 32);
#pragma unroll
            for (int jj = 0; jj < 4; jj++) {
                mma16816(s[2*jj],   qh[ks], kf[jj]);
                mma16816(s[2*jj+1], qh[ks], kf[jj] + 2);
            }
#pragma unroll
            for (int jj = 0; jj < 4; jj++) {
                mma16816(s[2*jj],   ql[ks], kf[jj]);
                mma16816(s[2*jj+1], ql[ks], kf[jj] + 2);
            }
#pragma unroll
            for (int jj = 0; jj < 4; jj++)
                ldsm_x4(kf[jj], kaddr + (FA_KLO - FA_KHI)
                                + jj * (16 * FA_PITCH) + ks * 32);
#pragma unroll
            for (int jj = 0; jj < 4; jj++) {
                mma16816(s[2*jj],   qh[ks], kf[jj]);
                mma16816(s[2*jj+1], qh[ks], kf[jj] + 2);
            }
        }

        // ---- causal mask (diagonal tile only; q pre-scaled by 1/sqrt(d))
        if (kb == qb) {
            const int rg0 = wid * 16 + r0;
#pragma unroll
            for (int j = 0; j < 8; j++) {
                int cg = j * 8 + c0;
                if (cg     > rg0)     s[j][0] = -CUDART_INF_F;
                if (cg + 1 > rg0)     s[j][1] = -CUDART_INF_F;
                if (cg     > rg0 + 8) s[j][2] = -CUDART_INF_F;
                if (cg + 1 > rg0 + 8) s[j][3] = -CUDART_INF_F;
            }
        }

        // ---- online softmax (rows r0, r0+8; 4-lane groups share a row)
        float mx0 = -CUDART_INF_F, mx1 = -CUDART_INF_F;
#pragma unroll
        for (int j = 0; j < 8; j++) {
            mx0 = fmaxf(mx0, fmaxf(s[j][0], s[j][1]));
            mx1 = fmaxf(mx1, fmaxf(s[j][2], s[j][3]));
        }
        mx0 = fmaxf(mx0, __shfl_xor_sync(0xffffffffu, mx0, 1));
        mx0 = fmaxf(mx0, __shfl_xor_sync(0xffffffffu, mx0, 2));
        mx1 = fmaxf(mx1, __shfl_xor_sync(0xffffffffu, mx1, 1));
        mx1 = fmaxf(mx1, __shfl_xor_sync(0xffffffffu, mx1, 2));

        float nm0 = fmaxf(m0r, mx0), nm1 = fmaxf(m1r, mx1);
        float co0 = __expf(m0r - nm0), co1 = __expf(m1r - nm1);
        m0r = nm0; m1r = nm1;

        uint32_t ph[8][2], pl[8][2];
        float sl0 = 0.f, sl1 = 0.f;
#pragma unroll
        for (int j = 0; j < 8; j++) {
            float p00 = __expf(s[j][0] - nm0), p01 = __expf(s[j][1] - nm0);
            float p10 = __expf(s[j][2] - nm1), p11 = __expf(s[j][3] - nm1);
            sl0 += p00 + p01;  sl1 += p10 + p11;
            ph[j][0] = pack2_hi(p00, p01);  pl[j][0] = pack2_lo(p00, p01);
            ph[j][1] = pack2_hi(p10, p11);  pl[j][1] = pack2_lo(p10, p11);
        }
        sl0 += __shfl_xor_sync(0xffffffffu, sl0, 1);
        sl0 += __shfl_xor_sync(0xffffffffu, sl0, 2);
        sl1 += __shfl_xor_sync(0xffffffffu, sl1, 1);
        sl1 += __shfl_xor_sync(0xffffffffu, sl1, 2);
        l0r = l0r * co0 + sl0;
        l1r = l1r * co1 + sl1;
#pragma unroll
        for (int n = 0; n < 16; n++) {
            yacc[n][0] *= co0; yacc[n][1] *= co0;
            yacc[n][2] *= co1; yacc[n][3] *= co1;
        }

        // ---- O += P V (3 passes)
#pragma unroll
        for (int t = 0; t < 4; t++) {
            uint32_t ah[4] = {ph[2*t][0], ph[2*t][1], ph[2*t+1][0], ph[2*t+1][1]};
            uint32_t al[4] = {pl[2*t][0], pl[2*t][1], pl[2*t+1][0], pl[2*t+1][1]};
#pragma unroll
            for (int half = 0; half < 2; half++) {
                uint32_t vf[4][4];
#pragma unroll
                for (int nn = 0; nn < 4; nn++)
                    ldsm_x4_t(vf[nn], vaddr + t * (16 * FA_PITCH)
                                      + (half * 4 + nn) * 32);
#pragma unroll
                for (int nn = 0; nn < 4; nn++) {
                    int n2 = (half * 4 + nn) * 2;
                    mma16816(yacc[n2],     ah, vf[nn]);
                    mma16816(yacc[n2 + 1], ah, vf[nn] + 2);
                }
#pragma unroll
                for (int nn = 0; nn < 4; nn++) {
                    int n2 = (half * 4 + nn) * 2;
                    mma16816(yacc[n2],     al, vf[nn]);
                    mma16816(yacc[n2 + 1], al, vf[nn] + 2);
                }
#pragma unroll
                for (int nn = 0; nn < 4; nn++)
                    ldsm_x4_t(vf[nn], vaddr + (FA_VLO - FA_VHI)
                                      + t * (16 * FA_PITCH)
                                      + (half * 4 + nn) * 32);
#pragma unroll
                for (int nn = 0; nn < 4; nn++) {
                    int n2 = (half * 4 + nn) * 2;
                    mma16816(yacc[n2],     ah, vf[nn]);
                    mma16816(yacc[n2 + 1], ah, vf[nn] + 2);
                }
            }
        }
    }

    // ---- finalize: y/l, split bf16 hi/lo, write [B,T,C] layout
    const float inv0 = 1.f / l0r, inv1 = 1.f / l1r;
    const int b = bh >> 4, h = bh & 15;
    const int t0 = qb * 64 + wid * 16 + r0;
    const size_t base0 = ((size_t)(b * TT + t0)) * CC + h * DD;
    const size_t base1 = base0 + (size_t)8 * CC;
#pragma unroll
    for (int n = 0; n < 16; n++) {
        int d0 = n * 8 + c0;
        float y00 = yacc[n][0] * inv0, y01 = yacc[n][1] * inv0;
        float y10 = yacc[n][2] * inv1, y11 = yacc[n][3] * inv1;
        *(uint32_t*)(g_yhi + base0 + d0) = pack2_hi(y00, y01);
        *(uint32_t*)(g_ylo + base0 + d0) = pack2_lo(y00, y01);
        *(uint32_t*)(g_yhi + base1 + d0) = pack2_hi(y10, y11);
        *(uint32_t*)(g_ylo + base1 + d0) = pack2_lo(y10, y11);
    }
}

// ============================================================================
extern "C" void kernel_launch(void* const* d_in, const int* in_sizes, int n_in,
                              void* d_out, int out_size)
{
    const float* x      = (const float*)d_in[0];   // [2,2048,2048]
    const float* w_attn = (const float*)d_in[1];   // [2048,6144]
    const float* w_proj = (const float*)d_in[2];   // [2048,2048]
    float* out = (float*)d_out;                    // [2,2048,2048]

    bf16 *xhi, *xlo, *yhi, *ylo, *wqhi, *wqlo, *wphi, *wplo;
    cudaGetSymbolAddress((void**)&xhi,  g_xhi);
    cudaGetSymbolAddress((void**)&xlo,  g_xlo);
    cudaGetSymbolAddress((void**)&yhi,  g_yhi);
    cudaGetSymbolAddress((void**)&ylo,  g_ylo);
    cudaGetSymbolAddress((void**)&wqhi, g_wqhi);
    cudaGetSymbolAddress((void**)&wqlo, g_wqlo);
    cudaGetSymbolAddress((void**)&wphi, g_wphi);
    cudaGetSymbolAddress((void**)&wplo, g_wplo);

    cudaFuncSetAttribute(gemm_bf16x3_kernel<0>,
                         cudaFuncAttributeMaxDynamicSharedMemorySize, GEMM_SMEM);
    cudaFuncSetAttribute(gemm_bf16x3_kernel<1>,
                         cudaFuncAttributeMaxDynamicSharedMemorySize, GEMM_SMEM);
    cudaFuncSetAttribute(flash_attn_mma_kernel,
                         cudaFuncAttributeMaxDynamicSharedMemorySize, FA_SMEM);

    // 0) prep: split x, transpose+split weights
    split_x_kernel<<<(size_t)MTOT * KDIM / 4 / 256, 256>>>(x, xhi, xlo);
    prep_w_kernel<<<dim3(N3C / 32, KDIM / 64), 256>>>(w_attn, wqhi, wqlo, N3C);
    prep_w_kernel<<<dim3(CC  / 32, KDIM / 64), 256>>>(w_proj, wphi, wplo, CC);

    // 1) QKV projection -> bf16 hi/lo q (pre-scaled), k, v
    gemm_bf16x3_kernel<0><<<dim3(N3C / 128, MTOT / 128), 256, GEMM_SMEM>>>(
        xhi, xlo, wqhi, wqlo, nullptr);

    // 2) causal flash attention (mma.sync bf16x3) -> g_yhi/g_ylo
    flash_attn_mma_kernel<<<dim3(TT / 64, BB * HH), 128, FA_SMEM>>>();

    // 3) output projection -> out
    gemm_bf16x3_kernel<1><<<dim3(CC / 128, MTOT / 128), 256, GEMM_SMEM>>>(
        yhi, ylo, wphi, wplo, out);
}

// round 5
// speedup vs baseline: 2.9350x; 1.0057x over previous
#include <cuda_runtime.h>
#include <cuda_bf16.h>
#include <math_constants.h>
#include <cstdint>

// Problem constants (B=2, T=2048, C=2048, H=16, D=128)
#define BB   2
#define TT   2048
#define CC   2048
#define HH   16
#define DD   128
#define MTOT (BB*TT)          // 4096
#define N3C  (3*CC)           // 6144
#define KDIM 2048

typedef __nv_bfloat16 bf16;

// -------- scratch (static device globals: the allowed scratch path) --------
__device__ bf16 g_qhi[(size_t)BB*HH*TT*DD];  // q pre-scaled, split
__device__ bf16 g_qlo[(size_t)BB*HH*TT*DD];
__device__ bf16 g_khi[(size_t)BB*HH*TT*DD];
__device__ bf16 g_klo[(size_t)BB*HH*TT*DD];
__device__ bf16 g_vhi[(size_t)BB*HH*TT*DD];
__device__ bf16 g_vlo[(size_t)BB*HH*TT*DD];
__device__ bf16 g_xhi[(size_t)MTOT*KDIM];    // x split
__device__ bf16 g_xlo[(size_t)MTOT*KDIM];
__device__ bf16 g_yhi[(size_t)MTOT*KDIM];    // attention out split
__device__ bf16 g_ylo[(size_t)MTOT*KDIM];
__device__ bf16 g_wqhi[(size_t)N3C*KDIM];    // w_attn^T split [N][K]
__device__ bf16 g_wqlo[(size_t)N3C*KDIM];
__device__ bf16 g_wphi[(size_t)CC*KDIM];     // w_proj^T split [N][K]
__device__ bf16 g_wplo[(size_t)CC*KDIM];

// ============================================================================
// helpers
// ============================================================================
__device__ __forceinline__ uint32_t smem_u32(const void* p) {
    uint32_t a;
    asm("{ .reg .u64 t; cvta.to.shared.u64 t, %1; cvt.u32.u64 %0, t; }"
        : "=r"(a) : "l"(p));
    return a;
}
__device__ __forceinline__ void split_bf16(float v, bf16& h, bf16& l) {
    h = __float2bfloat16_rn(v);
    l = __float2bfloat16_rn(v - __bfloat162float(h));
}
// returns (bf16(a) in low 16) | (bf16(b) in high 16)
__device__ __forceinline__ uint32_t pack2_hi(float a, float b) {
    uint32_t r;
    asm("cvt.rn.bf16x2.f32 %0, %1, %2;" : "=r"(r) : "f"(b), "f"(a));
    return r;
}
__device__ __forceinline__ uint32_t pack2_lo(float a, float b) {
    float ah = __bfloat162float(__float2bfloat16_rn(a));
    float bh = __bfloat162float(__float2bfloat16_rn(b));
    return pack2_hi(a - ah, b - bh);
}
#define CP16(dst, src) \
    asm volatile("cp.async.cg.shared.global [%0], [%1], 16;" \
                 :: "r"(dst), "l"(src))
#define CP_COMMIT() asm volatile("cp.async.commit_group;")
#define CP_WAIT(n)  asm volatile("cp.async.wait_group %0;" :: "n"(n))

__device__ __forceinline__ void ldsm_x4(uint32_t* r, uint32_t addr) {
    asm volatile("ldmatrix.sync.aligned.m8n8.x4.shared.b16 {%0,%1,%2,%3}, [%4];"
        : "=r"(r[0]), "=r"(r[1]), "=r"(r[2]), "=r"(r[3]) : "r"(addr));
}
__device__ __forceinline__ void ldsm_x4_t(uint32_t* r, uint32_t addr) {
    asm volatile("ldmatrix.sync.aligned.m8n8.x4.trans.shared.b16 {%0,%1,%2,%3}, [%4];"
        : "=r"(r[0]), "=r"(r[1]), "=r"(r[2]), "=r"(r[3]) : "r"(addr));
}
__device__ __forceinline__ void ldsm_x2(uint32_t* r, uint32_t addr) {
    asm volatile("ldmatrix.sync.aligned.m8n8.x2.shared.b16 {%0,%1}, [%2];"
        : "=r"(r[0]), "=r"(r[1]) : "r"(addr));
}
__device__ __forceinline__ void mma16816(float* c, const uint32_t* a,
                                         const uint32_t* b) {
    asm volatile(
        "mma.sync.aligned.m16n8k16.row.col.f32.bf16.bf16.f32 "
        "{%0,%1,%2,%3}, {%4,%5,%6,%7}, {%8,%9}, {%0,%1,%2,%3};"
        : "+f"(c[0]), "+f"(c[1]), "+f"(c[2]), "+f"(c[3])
        : "r"(a[0]), "r"(a[1]), "r"(a[2]), "r"(a[3]), "r"(b[0]), "r"(b[1]));
}

// ============================================================================
// Prep kernels
// ============================================================================
__global__ __launch_bounds__(256) void split_x_kernel(
    const float* __restrict__ X, bf16* __restrict__ Hi, bf16* __restrict__ Lo)
{
    size_t i4 = (size_t)blockIdx.x * 256 + threadIdx.x;
    float4 v = ((const float4*)X)[i4];
    bf16 h[4], l[4];
    split_bf16(v.x, h[0], l[0]); split_bf16(v.y, h[1], l[1]);
    split_bf16(v.z, h[2], l[2]); split_bf16(v.w, h[3], l[3]);
    *(uint2*)(Hi + i4 * 4) = *(uint2*)h;
    *(uint2*)(Lo + i4 * 4) = *(uint2*)l;
}

__global__ __launch_bounds__(256) void prep_w_kernel(
    const float* __restrict__ W, bf16* __restrict__ Hi, bf16* __restrict__ Lo,
    int N)
{
    __shared__ float s[32][65];           // [n][k] transposed
    const int k0 = blockIdx.y * 64;
    const int n0 = blockIdx.x * 32;
    const int tid = threadIdx.x;
    const int nn = tid & 31, kk = tid >> 5;
#pragma unroll
    for (int i = 0; i < 8; i++) {
        int k = kk + i * 8;
        s[nn][k] = __ldg(W + (size_t)(k0 + k) * N + n0 + nn);
    }
    __syncthreads();
    const int n = tid >> 3, kc = (tid & 7) * 8;
    bf16 h[8], l[8];
#pragma unroll
    for (int j = 0; j < 8; j++) split_bf16(s[n][kc + j], h[j], l[j]);
    size_t o = (size_t)(n0 + n) * KDIM + k0 + kc;
    *(uint4*)(Hi + o) = *(uint4*)h;
    *(uint4*)(Lo + o) = *(uint4*)l;
}

// ============================================================================
// bf16x3 GEMM via mma.sync: C[M,N] = A[M,K] @ B^T[N,K]
// Single-sync double-buffered pipeline: wait -> sync -> issue(c+1) -> MMA(c).
// MODE 0: split+scatter into g_{q,k,v}{hi,lo}; MODE 1: fp32 row-major Cout.
// ============================================================================
#define AH 0
#define AL 10240
#define BH 20480
#define BL 30720
#define STG 40960
#define GEMM_SMEM (2*STG)
#define NCHUNK (KDIM/32)      // 64

template<int MODE>
__global__ __launch_bounds__(256, 2) void gemm_bf16x3_kernel(
    const bf16* __restrict__ Ahi, const bf16* __restrict__ Alo,
    const bf16* __restrict__ Bhi, const bf16* __restrict__ Blo,
    float* __restrict__ Cout)
{
    extern __shared__ char smem[];
    const uint32_t sb = smem_u32(smem);
    const int tid  = threadIdx.x;
    const int lane = tid & 31, wid = tid >> 5;
    const int wm = wid & 1, wn = wid >> 1;       // warp grid 2 x 4
    const int m0 = blockIdx.y * 128;
    const int n0 = blockIdx.x * 128;

    float acc[4][4][4];
#pragma unroll
    for (int mi = 0; mi < 4; mi++)
#pragma unroll
        for (int ni = 0; ni < 4; ni++)
#pragma unroll
            for (int f = 0; f < 4; f++) acc[mi][ni][f] = 0.f;

    const uint32_t aBase = sb + AH + (wm * 64 + (lane & 15)) * 80
                         + (lane >> 4) * 16;
    const uint32_t bBase = sb + BH + (wn * 32 + (lane & 7)) * 80
                         + ((lane >> 3) & 1) * 16;

#define LOAD_CHUNK(c, st) do {                                                 \
    uint32_t s0 = sb + (st) * STG;                                             \
    _Pragma("unroll")                                                          \
    for (int p = 0; p < 2; p++) {                                              \
        int o   = tid + p * 256;                                               \
        int row = o >> 2, ch = o & 3;                                          \
        uint32_t dofs = row * 80 + ch * 16;                                    \
        size_t ga = (size_t)(m0 + row) * KDIM + (c) * 32 + ch * 8;             \
        size_t gb = (size_t)(n0 + row) * KDIM + (c) * 32 + ch * 8;             \
        CP16(s0 + AH + dofs, Ahi + ga);                                        \
        CP16(s0 + AL + dofs, Alo + ga);                                        \
        CP16(s0 + BH + dofs, Bhi + gb);                                        \
        CP16(s0 + BL + dofs, Blo + gb);                                        \
    }                                                                          \
} while (0)

    LOAD_CHUNK(0, 0);
    CP_COMMIT();

    for (int c = 0; c < NCHUNK; c++) {
        const int st = c & 1;
        CP_WAIT(0);               // chunk c resident (issued one iter ago)
        __syncthreads();          // visible to all; stage st^1 fully consumed
        if (c + 1 < NCHUNK) {     // overlap next chunk's loads with MMA(c)
            LOAD_CHUNK(c + 1, st ^ 1);
            CP_COMMIT();
        }

        const uint32_t sStage = st * STG;
#pragma unroll
        for (int ks = 0; ks < 2; ks++) {
            const uint32_t kOfs = sStage + ks * 32;
            uint32_t aw[4][4], bw[4][2], bw2[4][2];
#pragma unroll
            for (int mi = 0; mi < 4; mi++)
                ldsm_x4(aw[mi], aBase + kOfs + mi * (16 * 80));
#pragma unroll
            for (int ni = 0; ni < 4; ni++) {
                ldsm_x2(bw[ni],  bBase + kOfs + ni * (8 * 80));
                ldsm_x2(bw2[ni], bBase + kOfs + ni * (8 * 80) + (BL - BH));
            }
#pragma unroll
            for (int mi = 0; mi < 4; mi++)
#pragma unroll
                for (int ni = 0; ni < 4; ni++)
                    mma16816(acc[mi][ni], aw[mi], bw[ni]);
#pragma unroll
            for (int mi = 0; mi < 4; mi++)
#pragma unroll
                for (int ni = 0; ni < 4; ni++)
                    mma16816(acc[mi][ni], aw[mi], bw2[ni]);
#pragma unroll
            for (int mi = 0; mi < 4; mi++)
                ldsm_x4(aw[mi], aBase + kOfs + mi * (16 * 80) + (AL - AH));
#pragma unroll
            for (int mi = 0; mi < 4; mi++)
#pragma unroll
                for (int ni = 0; ni < 4; ni++)
                    mma16816(acc[mi][ni], aw[mi], bw[ni]);
        }
        // no trailing sync: next iteration's wait+sync covers reuse
    }

    // ---- epilogue ----
    const int lr = lane >> 2, lc = (lane & 3) * 2;
#pragma unroll
    for (int mi = 0; mi < 4; mi++) {
#pragma unroll
        for (int ni = 0; ni < 4; ni++) {
            int mrow = m0 + wm * 64 + mi * 16 + lr;
            int col  = wn * 32 + ni * 8 + lc;
            if (MODE == 0) {
                const int nb = blockIdx.x;
                const int which = nb >> 4, head = nb & 15;
                const float sc = (which == 0) ? 0.08838834764831845f : 1.0f;
                bf16 *hiB, *loB;
                if (which == 0)      { hiB = g_qhi; loB = g_qlo; }
                else if (which == 1) { hiB = g_khi; loB = g_klo; }
                else                 { hiB = g_vhi; loB = g_vlo; }
                int b0 = mrow >> 11, t0 = mrow & 2047;
                int m1 = mrow + 8;
                int b1 = m1 >> 11, t1 = m1 & 2047;
                size_t i0 = ((size_t)((b0 * HH + head) * TT + t0)) * DD + col;
                size_t i1 = ((size_t)((b1 * HH + head) * TT + t1)) * DD + col;
                float v0 = acc[mi][ni][0] * sc, v1 = acc[mi][ni][1] * sc;
                float v2 = acc[mi][ni][2] * sc, v3 = acc[mi][ni][3] * sc;
                *(uint32_t*)(hiB + i0) = pack2_hi(v0, v1);
                *(uint32_t*)(loB + i0) = pack2_lo(v0, v1);
                *(uint32_t*)(hiB + i1) = pack2_hi(v2, v3);
                *(uint32_t*)(loB + i1) = pack2_lo(v2, v3);
            } else {
                float* p0 = Cout + (size_t)mrow * CC + n0 + col;
                float* p1 = p0 + (size_t)8 * CC;
                *(float2*)p0 = make_float2(acc[mi][ni][0], acc[mi][ni][1]);
                *(float2*)p1 = make_float2(acc[mi][ni][2], acc[mi][ni][3]);
            }
        }
    }
#undef LOAD_CHUNK
}

// ============================================================================
// Flash attention on mma.sync (bf16x3). BM=BN=64, D=128, 4 warps, 2 CTAs/SM.
// K double-buffered; V + K(kb+1) loads issued at iter start, hidden under S.
// ============================================================================
#define FA_PITCH 272        // bytes per 128-bf16 row (256 + 16 pad)
#define FA_K0H 0
#define FA_K0L 17408
#define FA_K1H 34816
#define FA_K1L 52224
#define FA_VH  69632
#define FA_VL  87040
#define FA_SMEM 104448

__global__ __launch_bounds__(128, 2) void flash_attn_mma_kernel()
{
    extern __shared__ char smc[];
    const uint32_t sb = smem_u32(smc);
    const int tid  = threadIdx.x;
    const int lane = tid & 31, wid = tid >> 5;
    const int qb = (int)(gridDim.x - 1 - blockIdx.x);   // longest CTAs first
    const int bh = blockIdx.y;

    const size_t bhofs = (size_t)bh * TT * DD;
    const bf16* Qh = g_qhi + bhofs + (size_t)qb * 64 * DD;
    const bf16* Ql = g_qlo + bhofs + (size_t)qb * 64 * DD;

    // ---- stage Q into K1 region; preload K(0) into K0
#pragma unroll
    for (int p = 0; p < 8; p++) {
        int o = tid + p * 128;
        int row = o >> 4, ch = o & 15;
        uint32_t d = row * FA_PITCH + ch * 16;
        size_t g = (size_t)row * DD + ch * 8;
        CP16(sb + FA_K1H + d, Qh + g);
        CP16(sb + FA_K1L + d, Ql + g);
    }
    CP_COMMIT();
    {
        const bf16* Kh0 = g_khi + bhofs;
        const bf16* Kl0 = g_klo + bhofs;
#pragma unroll
        for (int p = 0; p < 8; p++) {
            int o = tid + p * 128;
            int row = o >> 4, ch = o & 15;
            uint32_t d = row * FA_PITCH + ch * 16;
            size_t g = (size_t)row * DD + ch * 8;
            CP16(sb + FA_K0H + d, Kh0 + g);
            CP16(sb + FA_K0L + d, Kl0 + g);
        }
    }
    CP_COMMIT();
    CP_WAIT(0);            // Q and K(0) resident
    __syncthreads();

    uint32_t qh[8][4], ql[8][4];
    {
        uint32_t qa = sb + FA_K1H + (wid * 16 + (lane & 15)) * FA_PITCH
                    + (lane >> 4) * 16;
#pragma unroll
        for (int ks = 0; ks < 8; ks++) {
            ldsm_x4(qh[ks], qa + ks * 32);
            ldsm_x4(ql[ks], qa + (FA_K1L - FA_K1H) + ks * 32);
        }
    }

    float yacc[16][4];
#pragma unroll
    for (int n = 0; n < 16; n++)
#pragma unroll
        for (int f = 0; f < 4; f++) yacc[n][f] = 0.f;
    float m0r = -CUDART_INF_F, m1r = -CUDART_INF_F;
    float l0r = 0.f, l1r = 0.f;

    const int r0 = lane >> 2;
    const int c0 = (lane & 3) * 2;

    // K (non-trans): rows = key
    const uint32_t laneK = ((lane & 7) + ((lane >> 4) & 1) * 8) * FA_PITCH
                         + ((lane >> 3) & 1) * 16;
    // V (trans): rows = key, col pairs of 8 d
    const uint32_t vaddr = sb + FA_VH
        + ((lane & 7) + ((lane >> 3) & 1) * 8) * FA_PITCH
        + ((lane >> 4) & 1) * 16;

    for (int kb = 0; kb <= qb; kb++) {
        const int cur = kb & 1;
        const uint32_t kaddr = sb + (cur ? FA_K1H : FA_K0H) + laneK;

        __syncthreads();   // A: all warps done with PV(kb-1) -> V region free,
                           //    K((kb+1)&1) buffer free
        // B: issue V(kb) and K(kb+1); they complete under the S section
        {
            const bf16* Vh = g_vhi + bhofs + (size_t)kb * 64 * DD;
            const bf16* Vl = g_vlo + bhofs + (size_t)kb * 64 * DD;
#pragma unroll
            for (int p = 0; p < 8; p++) {
                int o = tid + p * 128;
                int row = o >> 4, ch = o & 15;
                uint32_t d = row * FA_PITCH + ch * 16;
                size_t g = (size_t)row * DD + ch * 8;
                CP16(sb + FA_VH + d, Vh + g);
                CP16(sb + FA_VL + d, Vl + g);
            }
            if (kb < qb) {
                const uint32_t knext = (kb + 1) & 1 ? FA_K1H : FA_K0H;
                const bf16* Kh = g_khi + bhofs + (size_t)(kb + 1) * 64 * DD;
                const bf16* Kl = g_klo + bhofs + (size_t)(kb + 1) * 64 * DD;
#pragma unroll
                for (int p = 0; p < 8; p++) {
                    int o = tid + p * 128;
                    int row = o >> 4, ch = o & 15;
                    uint32_t d = row * FA_PITCH + ch * 16;
                    size_t g = (size_t)row * DD + ch * 8;
                    CP16(sb + knext + d, Kh + g);
                    CP16(sb + knext + (FA_K0L - FA_K0H) + d, Kl + g);
                }
            }
            CP_COMMIT();
        }

        // ---- C: S = Q K^T (3 passes) on K(kb) already resident
        float s[8][4];
#pragma unroll
        for (int j = 0; j < 8; j++)
#pragma unroll
            for (int f = 0; f < 4; f++) s[j][f] = 0.f;

#pragma unroll
        for (int ks = 0; ks < 8; ks++) {
            uint32_t kf[4][4];
#pragma unroll
            for (int jj = 0; jj < 4; jj++)
                ldsm_x4(kf[jj], kaddr + jj * (16 * FA_PITCH) + ks * 32);
#pragma unroll
            for (int jj = 0; jj < 4; jj++) {
                mma16816(s[2*jj],   qh[ks], kf[jj]);
                mma16816(s[2*jj+1], qh[ks], kf[jj] + 2);
            }
#pragma unroll
            for (int jj = 0; jj < 4; jj++) {
                mma16816(s[2*jj],   ql[ks], kf[jj]);
                mma16816(s[2*jj+1], ql[ks], kf[jj] + 2);
            }
#pragma unroll
            for (int jj = 0; jj < 4; jj++)
                ldsm_x4(kf[jj], kaddr + (FA_K0L - FA_K0H)
                                + jj * (16 * FA_PITCH) + ks * 32);
#pragma unroll
            for (int jj = 0; jj < 4; jj++) {
                mma16816(s[2*jj],   qh[ks], kf[jj]);
                mma16816(s[2*jj+1], qh[ks], kf[jj] + 2);
            }
        }

        // ---- D: causal mask + online softmax (register work, fills load time)
        if (kb == qb) {
            const int rg0 = wid * 16 + r0;
#pragma unroll
            for (int j = 0; j < 8; j++) {
                int cg = j * 8 + c0;
                if (cg     > rg0)     s[j][0] = -CUDART_INF_F;
                if (cg + 1 > rg0)     s[j][1] = -CUDART_INF_F;
                if (cg     > rg0 + 8) s[j][2] = -CUDART_INF_F;
                if (cg + 1 > rg0 + 8) s[j][3] = -CUDART_INF_F;
            }
        }

        float mx0 = -CUDART_INF_F, mx1 = -CUDART_INF_F;
#pragma unroll
        for (int j = 0; j < 8; j++) {
            mx0 = fmaxf(mx0, fmaxf(s[j][0], s[j][1]));
            mx1 = fmaxf(mx1, fmaxf(s[j][2], s[j][3]));
        }
        mx0 = fmaxf(mx0, __shfl_xor_sync(0xffffffffu, mx0, 1));
        mx0 = fmaxf(mx0, __shfl_xor_sync(0xffffffffu, mx0, 2));
        mx1 = fmaxf(mx1, __shfl_xor_sync(0xffffffffu, mx1, 1));
        mx1 = fmaxf(mx1, __shfl_xor_sync(0xffffffffu, mx1, 2));

        float nm0 = fmaxf(m0r, mx0), nm1 = fmaxf(m1r, mx1);
        float co0 = __expf(m0r - nm0), co1 = __expf(m1r - nm1);
        m0r = nm0; m1r = nm1;

        uint32_t ph[8][2], pl[8][2];
        float sl0 = 0.f, sl1 = 0.f;
#pragma unroll
        for (int j = 0; j < 8; j++) {
            float p00 = __expf(s[j][0] - nm0), p01 = __expf(s[j][1] - nm0);
            float p10 = __expf(s[j][2] - nm1), p11 = __expf(s[j][3] - nm1);
            sl0 += p00 + p01;  sl1 += p10 + p11;
            ph[j][0] = pack2_hi(p00, p01);  pl[j][0] = pack2_lo(p00, p01);
            ph[j][1] = pack2_hi(p10, p11);  pl[j][1] = pack2_lo(p10, p11);
        }
        sl0 += __shfl_xor_sync(0xffffffffu, sl0, 1);
        sl0 += __shfl_xor_sync(0xffffffffu, sl0, 2);
        sl1 += __shfl_xor_sync(0xffffffffu, sl1, 1);
        sl1 += __shfl_xor_sync(0xffffffffu, sl1, 2);
        l0r = l0r * co0 + sl0;
        l1r = l1r * co1 + sl1;
#pragma unroll
        for (int n = 0; n < 16; n++) {
            yacc[n][0] *= co0; yacc[n][1] *= co0;
            yacc[n][2] *= co1; yacc[n][3] *= co1;
        }

        // ---- E/F: V(kb) (and K(kb+1)) now resident; make visible to CTA
        CP_WAIT(0);
        __syncthreads();

        // ---- G: O += P V (3 passes)
#pragma unroll
        for (int t = 0; t < 4; t++) {
            uint32_t ah[4] = {ph[2*t][0], ph[2*t][1], ph[2*t+1][0], ph[2*t+1][1]};
            uint32_t al[4] = {pl[2*t][0], pl[2*t][1], pl[2*t+1][0], pl[2*t+1][1]};
#pragma unroll
            for (int half = 0; half < 2; half++) {
                uint32_t vf[4][4];
#pragma unroll
                for (int nn = 0; nn < 4; nn++)
                    ldsm_x4_t(vf[nn], vaddr + t * (16 * FA_PITCH)
                                      + (half * 4 + nn) * 32);
#pragma unroll
                for (int nn = 0; nn < 4; nn++) {
                    int n2 = (half * 4 + nn) * 2;
                    mma16816(yacc[n2],     ah, vf[nn]);
                    mma16816(yacc[n2 + 1], ah, vf[nn] + 2);
                }
#pragma unroll
                for (int nn = 0; nn < 4; nn++) {
                    int n2 = (half * 4 + nn) * 2;
                    mma16816(yacc[n2],     al, vf[nn]);
                    mma16816(yacc[n2 + 1], al, vf[nn] + 2);
                }
#pragma unroll
                for (int nn = 0; nn < 4; nn++)
                    ldsm_x4_t(vf[nn], vaddr + (FA_VL - FA_VH)
                                      + t * (16 * FA_PITCH)
                                      + (half * 4 + nn) * 32);
#pragma unroll
                for (int nn = 0; nn < 4; nn++) {
                    int n2 = (half * 4 + nn) * 2;
                    mma16816(yacc[n2],     ah, vf[nn]);
                    mma16816(yacc[n2 + 1], ah, vf[nn] + 2);
                }
            }
        }
    }

    // ---- finalize: y/l, split bf16 hi/lo, write [B,T,C] layout
    const float inv0 = 1.f / l0r, inv1 = 1.f / l1r;
    const int b = bh >> 4, h = bh & 15;
    const int t0 = qb * 64 + wid * 16 + r0;
    const size_t base0 = ((size_t)(b * TT + t0)) * CC + h * DD;
    const size_t base1 = base0 + (size_t)8 * CC;
#pragma unroll
    for (int n = 0; n < 16; n++) {
        int d0 = n * 8 + c0;
        float y00 = yacc[n][0] * inv0, y01 = yacc[n][1] * inv0;
        float y10 = yacc[n][2] * inv1, y11 = yacc[n][3] * inv1;
        *(uint32_t*)(g_yhi + base0 + d0) = pack2_hi(y00, y01);
        *(uint32_t*)(g_ylo + base0 + d0) = pack2_lo(y00, y01);
        *(uint32_t*)(g_yhi + base1 + d0) = pack2_hi(y10, y11);
        *(uint32_t*)(g_ylo + base1 + d0) = pack2_lo(y10, y11);
    }
}

// ============================================================================
extern "C" void kernel_launch(void* const* d_in, const int* in_sizes, int n_in,
                              void* d_out, int out_size)
{
    const float* x      = (const float*)d_in[0];   // [2,2048,2048]
    const float* w_attn = (const float*)d_in[1];   // [2048,6144]
    const float* w_proj = (const float*)d_in[2];   // [2048,2048]
    float* out = (float*)d_out;                    // [2,2048,2048]

    bf16 *xhi, *xlo, *yhi, *ylo, *wqhi, *wqlo, *wphi, *wplo;
    cudaGetSymbolAddress((void**)&xhi,  g_xhi);
    cudaGetSymbolAddress((void**)&xlo,  g_xlo);
    cudaGetSymbolAddress((void**)&yhi,  g_yhi);
    cudaGetSymbolAddress((void**)&ylo,  g_ylo);
    cudaGetSymbolAddress((void**)&wqhi, g_wqhi);
    cudaGetSymbolAddress((void**)&wqlo, g_wqlo);
    cudaGetSymbolAddress((void**)&wphi, g_wphi);
    cudaGetSymbolAddress((void**)&wplo, g_wplo);

    cudaFuncSetAttribute(gemm_bf16x3_kernel<0>,
                         cudaFuncAttributeMaxDynamicSharedMemorySize, GEMM_SMEM);
    cudaFuncSetAttribute(gemm_bf16x3_kernel<1>,
                         cudaFuncAttributeMaxDynamicSharedMemorySize, GEMM_SMEM);
    cudaFuncSetAttribute(flash_attn_mma_kernel,
                         cudaFuncAttributeMaxDynamicSharedMemorySize, FA_SMEM);

    // 0) prep: split x, transpose+split weights
    split_x_kernel<<<(size_t)MTOT * KDIM / 4 / 256, 256>>>(x, xhi, xlo);
    prep_w_kernel<<<dim3(N3C / 32, KDIM / 64), 256>>>(w_attn, wqhi, wqlo, N3C);
    prep_w_kernel<<<dim3(CC  / 32, KDIM / 64), 256>>>(w_proj, wphi, wplo, CC);

    // 1) QKV projection -> bf16 hi/lo q (pre-scaled), k, v
    gemm_bf16x3_kernel<0><<<dim3(N3C / 128, MTOT / 128), 256, GEMM_SMEM>>>(
        xhi, xlo, wqhi, wqlo, nullptr);

    // 2) causal flash attention (mma.sync bf16x3) -> g_yhi/g_ylo
    flash_attn_mma_kernel<<<dim3(TT / 64, BB * HH), 128, FA_SMEM>>>();

    // 3) output projection -> out
    gemm_bf16x3_kernel<1><<<dim3(CC / 128, MTOT / 128), 256, GEMM_SMEM>>>(
        yhi, ylo, wphi, wplo, out);
}

// round 6
// speedup vs baseline: 7.2616x; 2.4741x over previous
#include <cuda_runtime.h>
#include <cuda_fp16.h>
#include <math_constants.h>
#include <cstdint>

// Problem constants (B=2, T=2048, C=2048, H=16, D=128)
#define BB   2
#define TT   2048
#define CC   2048
#define HH   16
#define DD   128
#define MTOT (BB*TT)          // 4096
#define N3C  (3*CC)           // 6144
#define KDIM 2048

typedef __half fp16;

// -------- scratch (static device globals: the allowed scratch path) --------
__device__ fp16 g_q[(size_t)BB*HH*TT*DD];    // q pre-scaled by 1/sqrt(d)
__device__ fp16 g_k[(size_t)BB*HH*TT*DD];
__device__ fp16 g_v[(size_t)BB*HH*TT*DD];
__device__ fp16 g_x[(size_t)MTOT*KDIM];      // x as fp16
__device__ fp16 g_y[(size_t)MTOT*KDIM];      // attention out as fp16
__device__ fp16 g_wq[(size_t)N3C*KDIM];      // w_attn^T [N][K] fp16
__device__ fp16 g_wp[(size_t)CC*KDIM];       // w_proj^T [N][K] fp16

// ============================================================================
// helpers
// ============================================================================
__device__ __forceinline__ uint32_t smem_u32(const void* p) {
    uint32_t a;
    asm("{ .reg .u64 t; cvta.to.shared.u64 t, %1; cvt.u32.u64 %0, t; }"
        : "=r"(a) : "l"(p));
    return a;
}
// (fp16(a) in low 16) | (fp16(b) in high 16)
__device__ __forceinline__ uint32_t pack2_f16(float a, float b) {
    uint32_t r;
    asm("cvt.rn.f16x2.f32 %0, %1, %2;" : "=r"(r) : "f"(b), "f"(a));
    return r;
}
#define CP16(dst, src) \
    asm volatile("cp.async.cg.shared.global [%0], [%1], 16;" \
                 :: "r"(dst), "l"(src))
#define CP_COMMIT() asm volatile("cp.async.commit_group;")
#define CP_WAIT(n)  asm volatile("cp.async.wait_group %0;" :: "n"(n))

__device__ __forceinline__ void ldsm_x4(uint32_t* r, uint32_t addr) {
    asm volatile("ldmatrix.sync.aligned.m8n8.x4.shared.b16 {%0,%1,%2,%3}, [%4];"
        : "=r"(r[0]), "=r"(r[1]), "=r"(r[2]), "=r"(r[3]) : "r"(addr));
}
__device__ __forceinline__ void ldsm_x4_t(uint32_t* r, uint32_t addr) {
    asm volatile("ldmatrix.sync.aligned.m8n8.x4.trans.shared.b16 {%0,%1,%2,%3}, [%4];"
        : "=r"(r[0]), "=r"(r[1]), "=r"(r[2]), "=r"(r[3]) : "r"(addr));
}
__device__ __forceinline__ void ldsm_x2(uint32_t* r, uint32_t addr) {
    asm volatile("ldmatrix.sync.aligned.m8n8.x2.shared.b16 {%0,%1}, [%2];"
        : "=r"(r[0]), "=r"(r[1]) : "r"(addr));
}
__device__ __forceinline__ void mma16816(float* c, const uint32_t* a,
                                         const uint32_t* b) {
    asm volatile(
        "mma.sync.aligned.m16n8k16.row.col.f32.f16.f16.f32 "
        "{%0,%1,%2,%3}, {%4,%5,%6,%7}, {%8,%9}, {%0,%1,%2,%3};"
        : "+f"(c[0]), "+f"(c[1]), "+f"(c[2]), "+f"(c[3])
        : "r"(a[0]), "r"(a[1]), "r"(a[2]), "r"(a[3]), "r"(b[0]), "r"(b[1]));
}

// ============================================================================
// Prep kernels
// ============================================================================
__global__ __launch_bounds__(256) void conv_x_kernel(
    const float* __restrict__ X, fp16* __restrict__ O)
{
    size_t i4 = (size_t)blockIdx.x * 256 + threadIdx.x;
    float4 v = ((const float4*)X)[i4];
    uint32_t lo = pack2_f16(v.x, v.y);
    uint32_t hi = pack2_f16(v.z, v.w);
    *(uint2*)(O + i4 * 4) = make_uint2(lo, hi);
}

// W [K][N] fp32 -> W^T [N][K] fp16. Tile 64k x 32n.
__global__ __launch_bounds__(256) void prep_w_kernel(
    const float* __restrict__ W, fp16* __restrict__ O, int N)
{
    __shared__ float s[32][65];           // [n][k] transposed
    const int k0 = blockIdx.y * 64;
    const int n0 = blockIdx.x * 32;
    const int tid = threadIdx.x;
    const int nn = tid & 31, kk = tid >> 5;
#pragma unroll
    for (int i = 0; i < 8; i++) {
        int k = kk + i * 8;
        s[nn][k] = __ldg(W + (size_t)(k0 + k) * N + n0 + nn);
    }
    __syncthreads();
    const int n = tid >> 3, kc = (tid & 7) * 8;
    uint32_t o4[4];
#pragma unroll
    for (int j = 0; j < 4; j++)
        o4[j] = pack2_f16(s[n][kc + 2*j], s[n][kc + 2*j + 1]);
    size_t o = (size_t)(n0 + n) * KDIM + k0 + kc;
    *(uint4*)(O + o) = *(uint4*)o4;
}

// ============================================================================
// fp16 GEMM via mma.sync: C[M,N] = A[M,K] @ B^T[N,K]
// 128x128x32 CTA tile, 8 warps (2x4), single-sync double-buffered cp.async.
// MODE 0: scatter into g_q/g_k/g_v (fp16, q pre-scaled); MODE 1: fp32 Cout.
// ============================================================================
#define AOFF 0
#define BOFF 10240
#define STG  20480
#define GEMM_SMEM (2*STG)
#define NCHUNK (KDIM/32)      // 64

template<int MODE>
__global__ __launch_bounds__(256, 2) void gemm_fp16_kernel(
    const fp16* __restrict__ A, const fp16* __restrict__ B,
    float* __restrict__ Cout)
{
    extern __shared__ char smem[];
    const uint32_t sb = smem_u32(smem);
    const int tid  = threadIdx.x;
    const int lane = tid & 31, wid = tid >> 5;
    const int wm = wid & 1, wn = wid >> 1;       // warp grid 2 x 4
    const int m0 = blockIdx.y * 128;
    const int n0 = blockIdx.x * 128;

    float acc[4][4][4];
#pragma unroll
    for (int mi = 0; mi < 4; mi++)
#pragma unroll
        for (int ni = 0; ni < 4; ni++)
#pragma unroll
            for (int f = 0; f < 4; f++) acc[mi][ni][f] = 0.f;

    const uint32_t aBase = sb + AOFF + (wm * 64 + (lane & 15)) * 80
                         + (lane >> 4) * 16;
    const uint32_t bBase = sb + BOFF + (wn * 32 + (lane & 7)) * 80
                         + ((lane >> 3) & 1) * 16;

#define LOAD_CHUNK(c, st) do {                                                 \
    uint32_t s0 = sb + (st) * STG;                                             \
    _Pragma("unroll")                                                          \
    for (int p = 0; p < 2; p++) {                                              \
        int o   = tid + p * 256;                                               \
        int row = o >> 2, ch = o & 3;                                          \
        uint32_t dofs = row * 80 + ch * 16;                                    \
        size_t ga = (size_t)(m0 + row) * KDIM + (c) * 32 + ch * 8;             \
        size_t gb = (size_t)(n0 + row) * KDIM + (c) * 32 + ch * 8;             \
        CP16(s0 + AOFF + dofs, A + ga);                                        \
        CP16(s0 + BOFF + dofs, B + gb);                                        \
    }                                                                          \
} while (0)

    LOAD_CHUNK(0, 0);
    CP_COMMIT();

    for (int c = 0; c < NCHUNK; c++) {
        const int st = c & 1;
        CP_WAIT(0);
        __syncthreads();
        if (c + 1 < NCHUNK) {
            LOAD_CHUNK(c + 1, st ^ 1);
            CP_COMMIT();
        }

        const uint32_t sStage = st * STG;
#pragma unroll
        for (int ks = 0; ks < 2; ks++) {
            const uint32_t kOfs = sStage + ks * 32;
            uint32_t aw[4][4], bw[4][2];
#pragma unroll
            for (int mi = 0; mi < 4; mi++)
                ldsm_x4(aw[mi], aBase + kOfs + mi * (16 * 80));
#pragma unroll
            for (int ni = 0; ni < 4; ni++)
                ldsm_x2(bw[ni], bBase + kOfs + ni * (8 * 80));
#pragma unroll
            for (int mi = 0; mi < 4; mi++)
#pragma unroll
                for (int ni = 0; ni < 4; ni++)
                    mma16816(acc[mi][ni], aw[mi], bw[ni]);
        }
    }

    // ---- epilogue ----
    const int lr = lane >> 2, lc = (lane & 3) * 2;
#pragma unroll
    for (int mi = 0; mi < 4; mi++) {
#pragma unroll
        for (int ni = 0; ni < 4; ni++) {
            int mrow = m0 + wm * 64 + mi * 16 + lr;
            int col  = wn * 32 + ni * 8 + lc;
            if (MODE == 0) {
                const int nb = blockIdx.x;
                const int which = nb >> 4, head = nb & 15;
                const float sc = (which == 0) ? 0.08838834764831845f : 1.0f;
                fp16* base = (which == 0) ? g_q : (which == 1) ? g_k : g_v;
                int b0 = mrow >> 11, t0 = mrow & 2047;
                int m1 = mrow + 8;
                int b1 = m1 >> 11, t1 = m1 & 2047;
                size_t i0 = ((size_t)((b0 * HH + head) * TT + t0)) * DD + col;
                size_t i1 = ((size_t)((b1 * HH + head) * TT + t1)) * DD + col;
                *(uint32_t*)(base + i0) =
                    pack2_f16(acc[mi][ni][0] * sc, acc[mi][ni][1] * sc);
                *(uint32_t*)(base + i1) =
                    pack2_f16(acc[mi][ni][2] * sc, acc[mi][ni][3] * sc);
            } else {
                float* p0 = Cout + (size_t)mrow * CC + n0 + col;
                float* p1 = p0 + (size_t)8 * CC;
                *(float2*)p0 = make_float2(acc[mi][ni][0], acc[mi][ni][1]);
                *(float2*)p1 = make_float2(acc[mi][ni][2], acc[mi][ni][3]);
            }
        }
    }
#undef LOAD_CHUNK
}

// ============================================================================
// Flash attention on mma.sync (fp16). BM=BN=64, D=128, 4 warps, 2 CTAs/SM.
// K double-buffered; V(kb) + K(kb+1) issued at iter start, hidden under S.
// ============================================================================
#define FA_PITCH 272        // bytes per 128-fp16 row (256 + 16 pad)
#define FA_K0 0
#define FA_K1 17408
#define FA_V  34816
#define FA_SMEM 52224

__global__ __launch_bounds__(128, 2) void flash_attn_mma_kernel()
{
    extern __shared__ char smc[];
    const uint32_t sb = smem_u32(smc);
    const int tid  = threadIdx.x;
    const int lane = tid & 31, wid = tid >> 5;
    const int qb = (int)(gridDim.x - 1 - blockIdx.x);   // longest CTAs first
    const int bh = blockIdx.y;

    const size_t bhofs = (size_t)bh * TT * DD;
    const fp16* Qg = g_q + bhofs + (size_t)qb * 64 * DD;

    // ---- stage Q into K1 region, preload K(0) into K0
#pragma unroll
    for (int p = 0; p < 8; p++) {
        int o = tid + p * 128;
        int row = o >> 4, ch = o & 15;
        uint32_t d = row * FA_PITCH + ch * 16;
        size_t g = (size_t)row * DD + ch * 8;
        CP16(sb + FA_K1 + d, Qg + g);
        CP16(sb + FA_K0 + d, g_k + bhofs + g);
    }
    CP_COMMIT();
    CP_WAIT(0);
    __syncthreads();

    uint32_t qf[8][4];
    {
        uint32_t qa = sb + FA_K1 + (wid * 16 + (lane & 15)) * FA_PITCH
                    + (lane >> 4) * 16;
#pragma unroll
        for (int ks = 0; ks < 8; ks++)
            ldsm_x4(qf[ks], qa + ks * 32);
    }

    float yacc[16][4];
#pragma unroll
    for (int n = 0; n < 16; n++)
#pragma unroll
        for (int f = 0; f < 4; f++) yacc[n][f] = 0.f;
    float m0r = -CUDART_INF_F, m1r = -CUDART_INF_F;
    float l0r = 0.f, l1r = 0.f;

    const int r0 = lane >> 2;
    const int c0 = (lane & 3) * 2;

    const uint32_t laneK = ((lane & 7) + ((lane >> 4) & 1) * 8) * FA_PITCH
                         + ((lane >> 3) & 1) * 16;
    const uint32_t vaddr = sb + FA_V
        + ((lane & 7) + ((lane >> 3) & 1) * 8) * FA_PITCH
        + ((lane >> 4) & 1) * 16;

    for (int kb = 0; kb <= qb; kb++) {
        const uint32_t kaddr = sb + ((kb & 1) ? FA_K1 : FA_K0) + laneK;

        __syncthreads();   // PV(kb-1) consumed; V region + next-K buffer free
        {
            const fp16* Vg = g_v + bhofs + (size_t)kb * 64 * DD;
#pragma unroll
            for (int p = 0; p < 8; p++) {
                int o = tid + p * 128;
                int row = o >> 4, ch = o & 15;
                uint32_t d = row * FA_PITCH + ch * 16;
                size_t g = (size_t)row * DD + ch * 8;
                CP16(sb + FA_V + d, Vg + g);
            }
            if (kb < qb) {
                const uint32_t knext = sb + (((kb + 1) & 1) ? FA_K1 : FA_K0);
                const fp16* Kg = g_k + bhofs + (size_t)(kb + 1) * 64 * DD;
#pragma unroll
                for (int p = 0; p < 8; p++) {
                    int o = tid + p * 128;
                    int row = o >> 4, ch = o & 15;
                    uint32_t d = row * FA_PITCH + ch * 16;
                    size_t g = (size_t)row * DD + ch * 8;
                    CP16(knext + d, Kg + g);
                }
            }
            CP_COMMIT();
        }

        // ---- S = Q K^T on resident K(kb)
        float s[8][4];
#pragma unroll
        for (int j = 0; j < 8; j++)
#pragma unroll
            for (int f = 0; f < 4; f++) s[j][f] = 0.f;

#pragma unroll
        for (int ks = 0; ks < 8; ks++) {
            uint32_t kf[4][4];
#pragma unroll
            for (int jj = 0; jj < 4; jj++)
                ldsm_x4(kf[jj], kaddr + jj * (16 * FA_PITCH) + ks * 32);
#pragma unroll
            for (int jj = 0; jj < 4; jj++) {
                mma16816(s[2*jj],   qf[ks], kf[jj]);
                mma16816(s[2*jj+1], qf[ks], kf[jj] + 2);
            }
        }

        // ---- causal mask + online softmax
        if (kb == qb) {
            const int rg0 = wid * 16 + r0;
#pragma unroll
            for (int j = 0; j < 8; j++) {
                int cg = j * 8 + c0;
                if (cg     > rg0)     s[j][0] = -CUDART_INF_F;
                if (cg + 1 > rg0)     s[j][1] = -CUDART_INF_F;
                if (cg     > rg0 + 8) s[j][2] = -CUDART_INF_F;
                if (cg + 1 > rg0 + 8) s[j][3] = -CUDART_INF_F;
            }
        }

        float mx0 = -CUDART_INF_F, mx1 = -CUDART_INF_F;
#pragma unroll
        for (int j = 0; j < 8; j++) {
            mx0 = fmaxf(mx0, fmaxf(s[j][0], s[j][1]));
            mx1 = fmaxf(mx1, fmaxf(s[j][2], s[j][3]));
        }
        mx0 = fmaxf(mx0, __shfl_xor_sync(0xffffffffu, mx0, 1));
        mx0 = fmaxf(mx0, __shfl_xor_sync(0xffffffffu, mx0, 2));
        mx1 = fmaxf(mx1, __shfl_xor_sync(0xffffffffu, mx1, 1));
        mx1 = fmaxf(mx1, __shfl_xor_sync(0xffffffffu, mx1, 2));

        float nm0 = fmaxf(m0r, mx0), nm1 = fmaxf(m1r, mx1);
        float co0 = __expf(m0r - nm0), co1 = __expf(m1r - nm1);
        m0r = nm0; m1r = nm1;

        uint32_t pp[8][2];
        float sl0 = 0.f, sl1 = 0.f;
#pragma unroll
        for (int j = 0; j < 8; j++) {
            float p00 = __expf(s[j][0] - nm0), p01 = __expf(s[j][1] - nm0);
            float p10 = __expf(s[j][2] - nm1), p11 = __expf(s[j][3] - nm1);
            sl0 += p00 + p01;  sl1 += p10 + p11;
            pp[j][0] = pack2_f16(p00, p01);
            pp[j][1] = pack2_f16(p10, p11);
        }
        sl0 += __shfl_xor_sync(0xffffffffu, sl0, 1);
        sl0 += __shfl_xor_sync(0xffffffffu, sl0, 2);
        sl1 += __shfl_xor_sync(0xffffffffu, sl1, 1);
        sl1 += __shfl_xor_sync(0xffffffffu, sl1, 2);
        l0r = l0r * co0 + sl0;
        l1r = l1r * co1 + sl1;
#pragma unroll
        for (int n = 0; n < 16; n++) {
            yacc[n][0] *= co0; yacc[n][1] *= co0;
            yacc[n][2] *= co1; yacc[n][3] *= co1;
        }

        // ---- V(kb) resident; make visible
        CP_WAIT(0);
        __syncthreads();

        // ---- O += P V
#pragma unroll
        for (int t = 0; t < 4; t++) {
            uint32_t ap[4] = {pp[2*t][0], pp[2*t][1], pp[2*t+1][0], pp[2*t+1][1]};
#pragma unroll
            for (int half = 0; half < 2; half++) {
                uint32_t vf[4][4];
#pragma unroll
                for (int nn = 0; nn < 4; nn++)
                    ldsm_x4_t(vf[nn], vaddr + t * (16 * FA_PITCH)
                                      + (half * 4 + nn) * 32);
#pragma unroll
                for (int nn = 0; nn < 4; nn++) {
                    int n2 = (half * 4 + nn) * 2;
                    mma16816(yacc[n2],     ap, vf[nn]);
                    mma16816(yacc[n2 + 1], ap, vf[nn] + 2);
                }
            }
        }
    }

    // ---- finalize: y/l as fp16 into [B,T,C] layout
    const float inv0 = 1.f / l0r, inv1 = 1.f / l1r;
    const int b = bh >> 4, h = bh & 15;
    const int t0 = qb * 64 + wid * 16 + r0;
    const size_t base0 = ((size_t)(b * TT + t0)) * CC + h * DD;
    const size_t base1 = base0 + (size_t)8 * CC;
#pragma unroll
    for (int n = 0; n < 16; n++) {
        int d0 = n * 8 + c0;
        *(uint32_t*)(g_y + base0 + d0) =
            pack2_f16(yacc[n][0] * inv0, yacc[n][1] * inv0);
        *(uint32_t*)(g_y + base1 + d0) =
            pack2_f16(yacc[n][2] * inv1, yacc[n][3] * inv1);
    }
}

// ============================================================================
extern "C" void kernel_launch(void* const* d_in, const int* in_sizes, int n_in,
                              void* d_out, int out_size)
{
    const float* x      = (const float*)d_in[0];   // [2,2048,2048]
    const float* w_attn = (const float*)d_in[1];   // [2048,6144]
    const float* w_proj = (const float*)d_in[2];   // [2048,2048]
    float* out = (float*)d_out;                    // [2,2048,2048]

    fp16 *xh, *yh, *wqh, *wph;
    cudaGetSymbolAddress((void**)&xh,  g_x);
    cudaGetSymbolAddress((void**)&yh,  g_y);
    cudaGetSymbolAddress((void**)&wqh, g_wq);
    cudaGetSymbolAddress((void**)&wph, g_wp);

    cudaFuncSetAttribute(gemm_fp16_kernel<0>,
                         cudaFuncAttributeMaxDynamicSharedMemorySize, GEMM_SMEM);
    cudaFuncSetAttribute(gemm_fp16_kernel<1>,
                         cudaFuncAttributeMaxDynamicSharedMemorySize, GEMM_SMEM);
    cudaFuncSetAttribute(flash_attn_mma_kernel,
                         cudaFuncAttributeMaxDynamicSharedMemorySize, FA_SMEM);

    // 0) prep: convert x, transpose+convert weights
    conv_x_kernel<<<(size_t)MTOT * KDIM / 4 / 256, 256>>>(x, xh);
    prep_w_kernel<<<dim3(N3C / 32, KDIM / 64), 256>>>(w_attn, wqh, N3C);
    prep_w_kernel<<<dim3(CC  / 32, KDIM / 64), 256>>>(w_proj, wph, CC);

    // 1) QKV projection -> fp16 q (pre-scaled), k, v
    gemm_fp16_kernel<0><<<dim3(N3C / 128, MTOT / 128), 256, GEMM_SMEM>>>(
        xh, wqh, nullptr);

    // 2) causal flash attention (mma.sync fp16) -> g_y
    flash_attn_mma_kernel<<<dim3(TT / 64, BB * HH), 128, FA_SMEM>>>();

    // 3) output projection -> out (fp32)
    gemm_fp16_kernel<1><<<dim3(CC / 128, MTOT / 128), 256, GEMM_SMEM>>>(
        yh, wph, out);
}